// round 1
// baseline (speedup 1.0000x reference)
#include <cuda_runtime.h>
#include <mma.h>

using namespace nvcuda;

// Problem constants (fixed shapes for this problem)
#define NTOK  8192        // B*T = 4*2048
#define DIM   1024        // D == H == 1024
#define NE    8           // experts
#define MAXK  8           // max supported topn
#define SLAB  8320        // 8192 + 128 pad rows per expert (tile-store overflow space)

#define BM 128
#define BN 128
#define BK 32
#define KDIM 1024

// ---------------- scratch (device globals; no allocation allowed) ----------
__device__ int   g_count[NE];
__device__ int   g_tok [NE * NTOK];          // token index per (expert, slot)
__device__ int   g_slot[NTOK * MAXK];        // global row (e*SLAB+slot) per (token, k)
__device__ float g_wt  [NTOK * MAXK];        // combine weight per (token, k)
__device__ float g_h1  [(size_t)NE * SLAB * DIM];  // layer1 out, later reused as eo
__device__ float g_h2  [(size_t)NE * SLAB * DIM];  // layer2 out

// ---------------- helpers ---------------------------------------------------
__device__ __forceinline__ int load_topn(const void* p) {
    int v = *(const int*)p;
    if (v >= 1 && v <= MAXK) return v;
    float f = *(const float*)p;           // hedge: topn delivered as float
    int vi = (int)(f + 0.5f);
    if (vi >= 1 && vi <= MAXK) return vi;
    return 2;
}

// ---------------- init ------------------------------------------------------
__global__ void init_kernel() {
    if (threadIdx.x < NE) g_count[threadIdx.x] = 0;
}

// ---------------- gating: one warp per token -------------------------------
__global__ void gating_kernel(const float* __restrict__ x,
                              const float* __restrict__ gw,   // [DIM, NE]
                              const float* __restrict__ gb,   // [NE]
                              const void*  __restrict__ topn_p) {
    int wid  = threadIdx.x >> 5;
    int lane = threadIdx.x & 31;
    int t = blockIdx.x * (blockDim.x >> 5) + wid;
    if (t >= NTOK) return;

    float acc[NE];
#pragma unroll
    for (int e = 0; e < NE; e++) acc[e] = 0.f;

    const float* xr = x + (size_t)t * DIM;
    for (int d = lane; d < DIM; d += 32) {
        float xv = xr[d];
#pragma unroll
        for (int e = 0; e < NE; e++) acc[e] += xv * gw[d * NE + e];
    }
#pragma unroll
    for (int e = 0; e < NE; e++) {
        float v = acc[e];
#pragma unroll
        for (int o = 16; o; o >>= 1) v += __shfl_xor_sync(0xffffffffu, v, o);
        acc[e] = v;
    }

    if (lane == 0) {
        float logit[NE];
#pragma unroll
        for (int e = 0; e < NE; e++) logit[e] = acc[e] + gb[e];

        int tn = load_topn(topn_p);

        int   sel[MAXK];
        float sl [MAXK];
        bool  used[NE];
#pragma unroll
        for (int e = 0; e < NE; e++) used[e] = false;

        for (int k = 0; k < tn; k++) {
            int best = -1; float bv = -3.4e38f;
#pragma unroll
            for (int e = 0; e < NE; e++) {
                if (!used[e] && logit[e] > bv) { bv = logit[e]; best = e; }
            }
            used[best] = true;
            sel[k] = best;
            sl[k]  = bv;
        }
        // softmax over selected logits == softmax(all) -> mask -> L1 renorm
        float m = sl[0];                  // first pick is the global max
        float s = 0.f;
        for (int k = 0; k < tn; k++) { sl[k] = expf(sl[k] - m); s += sl[k]; }
        float inv = 1.f / s;

        for (int k = 0; k < tn; k++) {
            int e = sel[k];
            int slot = atomicAdd(&g_count[e], 1);
            g_tok [e * NTOK + slot] = t;
            g_slot[t * MAXK + k]    = e * SLAB + slot;
            g_wt  [t * MAXK + k]    = sl[k] * inv;
        }
    }
}

// ---------------- grouped GEMM (tf32 wmma), bias folded as extra K step ----
// mode 0: A = gather x rows via g_tok, Out = g_h1, LeakyReLU
// mode 1: A = g_h1 rows,              Out = g_h2, LeakyReLU
// mode 2: A = g_h2 rows,              Out = g_h1 (eo), no activation
__global__ __launch_bounds__(256, 2)
void moe_gemm(const float* __restrict__ x,
              const float* __restrict__ W,     // [NE][KDIM][DIM] row-major
              const float* __restrict__ bias,  // [NE][DIM]
              int mode) {
    int e = blockIdx.z;
    int cnt = g_count[e];
    int mbase = blockIdx.y * BM;
    if (mbase >= cnt) return;
    int nbase = blockIdx.x * BN;

    const float* Wb = W + (size_t)e * KDIM * DIM;
    const float* Bb = bias + (size_t)e * DIM;
    const float* Asrc = (mode == 1) ? g_h1 : g_h2;
    float* Out = (mode == 1) ? g_h2 : g_h1;

    __shared__ float As[BM][BK];
    __shared__ float Bs[BK][BN];
    __shared__ const float* Arow[BM];

    int tid = threadIdx.x;
    for (int i = tid; i < BM; i += 256) {
        int m = mbase + i;
        const float* p = nullptr;
        if (m < cnt) {
            if (mode == 0) p = x + (size_t)g_tok[e * NTOK + m] * DIM;
            else           p = Asrc + ((size_t)e * SLAB + m) * DIM;
        }
        Arow[i] = p;
    }
    __syncthreads();

    wmma::fragment<wmma::accumulator, 16, 16, 8, float> c[4][2];
#pragma unroll
    for (int i = 0; i < 4; i++)
#pragma unroll
        for (int j = 0; j < 2; j++) wmma::fill_fragment(c[i][j], 0.f);

    int wid = tid >> 5;
    int wm = (wid >> 2) * 64;   // 0 or 64
    int wn = (wid & 3) * 32;    // 0,32,64,96

    const int KSTEPS = KDIM / BK;  // 32; iteration KSTEPS is the bias step
    for (int kt = 0; kt <= KSTEPS; ++kt) {
        int k0 = kt * BK;
        // load A tile (128x32)
#pragma unroll
        for (int j = 0; j < 4; j++) {
            int idx = tid + j * 256;       // 0..1023
            int r = idx >> 3;
            int c4 = (idx & 7) * 4;
            float4 v = make_float4(0.f, 0.f, 0.f, 0.f);
            const float* p = Arow[r];
            if (kt < KSTEPS) {
                if (p) v = *(const float4*)(p + k0 + c4);
            } else {
                if (c4 == 0 && p) v.x = 1.f;   // ones column for bias
            }
            *(float4*)&As[r][c4] = v;
        }
        // load B tile (32x128)
#pragma unroll
        for (int j = 0; j < 4; j++) {
            int idx = tid + j * 256;
            int r = idx >> 5;
            int c4 = (idx & 31) * 4;
            float4 v;
            if (kt < KSTEPS) {
                v = *(const float4*)(Wb + (size_t)(k0 + r) * DIM + nbase + c4);
            } else {
                if (r == 0) v = *(const float4*)(Bb + nbase + c4);
                else        v = make_float4(0.f, 0.f, 0.f, 0.f);
            }
            *(float4*)&Bs[r][c4] = v;
        }
        __syncthreads();

#pragma unroll
        for (int ks = 0; ks < 4; ++ks) {
            wmma::fragment<wmma::matrix_a, 16, 16, 8, wmma::precision::tf32, wmma::row_major> a[4];
            wmma::fragment<wmma::matrix_b, 16, 16, 8, wmma::precision::tf32, wmma::row_major> b[2];
#pragma unroll
            for (int i = 0; i < 4; i++) {
                wmma::load_matrix_sync(a[i], &As[wm + i * 16][ks * 8], BK);
#pragma unroll
                for (int tt = 0; tt < a[i].num_elements; tt++)
                    a[i].x[tt] = wmma::__float_to_tf32(a[i].x[tt]);
            }
#pragma unroll
            for (int j = 0; j < 2; j++) {
                wmma::load_matrix_sync(b[j], &Bs[ks * 8][wn + j * 16], BN);
#pragma unroll
                for (int tt = 0; tt < b[j].num_elements; tt++)
                    b[j].x[tt] = wmma::__float_to_tf32(b[j].x[tt]);
            }
#pragma unroll
            for (int i = 0; i < 4; i++)
#pragma unroll
                for (int j = 0; j < 2; j++)
                    wmma::mma_sync(c[i][j], a[i], b[j], c[i][j]);
        }
        __syncthreads();
    }

    // epilogue: optional LeakyReLU on fragment elements, store direct to global
    bool act = (mode != 2);
#pragma unroll
    for (int i = 0; i < 4; i++) {
#pragma unroll
        for (int j = 0; j < 2; j++) {
            if (act) {
#pragma unroll
                for (int tt = 0; tt < c[i][j].num_elements; tt++) {
                    float v = c[i][j].x[tt];
                    c[i][j].x[tt] = (v >= 0.f) ? v : 0.01f * v;
                }
            }
            size_t row = (size_t)e * SLAB + mbase + wm + i * 16;  // pad keeps this in-slab
            wmma::store_matrix_sync(Out + row * DIM + nbase + wn + j * 16,
                                    c[i][j], DIM, wmma::mem_row_major);
        }
    }
}

// ---------------- deterministic combine ------------------------------------
__global__ void combine_kernel(float* __restrict__ out,
                               const void* __restrict__ topn_p) {
    int tn = load_topn(topn_p);
    size_t idx = (size_t)blockIdx.x * blockDim.x + threadIdx.x;
    if (idx >= (size_t)NTOK * DIM) return;
    int t = (int)(idx >> 10);
    int d = (int)(idx & (DIM - 1));
    float acc = 0.f;
    for (int k = 0; k < tn; k++) {
        int slot = g_slot[t * MAXK + k];
        acc += g_wt[t * MAXK + k] * g_h1[(size_t)slot * DIM + d];  // g_h1 holds eo
    }
    out[idx] = acc;
}

// ---------------- launch ----------------------------------------------------
extern "C" void kernel_launch(void* const* d_in, const int* in_sizes, int n_in,
                              void* d_out, int out_size) {
    const float* x   = (const float*)d_in[0];
    const float* gw  = (const float*)d_in[1];
    const float* gb  = (const float*)d_in[2];
    const float* w1  = (const float*)d_in[3];
    const float* b1  = (const float*)d_in[4];
    const float* w2  = (const float*)d_in[5];
    const float* b2  = (const float*)d_in[6];
    const float* w3  = (const float*)d_in[7];
    const float* b3  = (const float*)d_in[8];
    const void*  tp  = d_in[9];
    float* out = (float*)d_out;

    init_kernel<<<1, 32>>>();
    gating_kernel<<<NTOK / 8, 256>>>(x, gw, gb, tp);

    dim3 grid(DIM / BN, (NTOK + BM - 1) / BM, NE);   // (8, 64, 8)
    moe_gemm<<<grid, 256>>>(x, w1, b1, 0);
    moe_gemm<<<grid, 256>>>(x, w2, b2, 1);
    moe_gemm<<<grid, 256>>>(x, w3, b3, 2);

    combine_kernel<<<(NTOK * DIM + 255) / 256, 256>>>(out, tp);
}

// round 3
// speedup vs baseline: 3.7150x; 3.7150x over previous
#include <cuda_runtime.h>
#include <cstdint>

// Problem constants
#define NTOK  8192
#define DIM   1024
#define NE    8
#define MAXK  8
#define SLAB  8320
#define KDIM  1024

// GEMM tiling
#define BM 128
#define BN 256
#define BK 32
#define KSTEPS (KDIM / BK)   // 32
#define STAGES 3
#define ASZ (BM * BK * 4)    // 16384 B
#define BSZ (BK * BN * 4)    // 32768 B

// dynamic smem layout
#define SM_AROW 0                         // 128 x 8B row pointers
#define SM_ASZT 1024                      // 128 x 4B per-row cp.async sizes
#define SM_A    2048
#define SM_B    (SM_A + STAGES * ASZ)
#define SMEM_TOTAL (SM_B + STAGES * BSZ)  // 149504 B

// ---------------- scratch (device globals) ----------------------------------
__device__ int   g_count[NE];
__device__ int   g_tok [NE * NTOK];
__device__ int   g_slot[NTOK * MAXK];
__device__ float g_wt  [NTOK * MAXK];
__device__ float g_h1  [(size_t)NE * SLAB * DIM];
__device__ float g_h2  [(size_t)NE * SLAB * DIM];

// ---------------- PTX helpers ------------------------------------------------
__device__ __forceinline__ uint32_t smem_u32(const void* p) {
    uint32_t a;
    asm("{ .reg .u64 t; cvta.to.shared.u64 t, %1; cvt.u32.u64 %0, t; }" : "=r"(a) : "l"(p));
    return a;
}

__device__ __forceinline__ void cp_async16(uint32_t dst, const void* src, uint32_t sz) {
    asm volatile("cp.async.cg.shared.global [%0], [%1], 16, %2;"
                 :: "r"(dst), "l"(src), "r"(sz) : "memory");
}
#define CP_COMMIT() asm volatile("cp.async.commit_group;" ::: "memory")
#define CP_WAIT1()  asm volatile("cp.async.wait_group 1;" ::: "memory")

__device__ __forceinline__ uint32_t lds_cvt(uint32_t addr) {
    uint32_t v, t;
    asm volatile("ld.shared.b32 %0, [%1];" : "=r"(v) : "r"(addr));
    asm volatile("cvt.rna.tf32.f32 %0, %1;" : "=r"(t) : "r"(v));
    return t;
}

__device__ __forceinline__ void mma8(float* c, uint32_t a0, uint32_t a1, uint32_t a2,
                                     uint32_t a3, uint32_t b0, uint32_t b1) {
    asm volatile(
        "mma.sync.aligned.m16n8k8.row.col.f32.tf32.tf32.f32 "
        "{%0,%1,%2,%3}, {%4,%5,%6,%7}, {%8,%9}, {%0,%1,%2,%3};"
        : "+f"(c[0]), "+f"(c[1]), "+f"(c[2]), "+f"(c[3])
        : "r"(a0), "r"(a1), "r"(a2), "r"(a3), "r"(b0), "r"(b1));
}

// ---------------- misc helpers -----------------------------------------------
__device__ __forceinline__ int load_topn(const void* p) {
    int v = *(const int*)p;
    if (v >= 1 && v <= MAXK) return v;
    float f = *(const float*)p;
    int vi = (int)(f + 0.5f);
    if (vi >= 1 && vi <= MAXK) return vi;
    return 2;
}

__global__ void init_kernel() {
    if (threadIdx.x < NE) g_count[threadIdx.x] = 0;
}

// ---------------- gating: one warp per token ---------------------------------
__global__ void gating_kernel(const float* __restrict__ x,
                              const float* __restrict__ gw,
                              const float* __restrict__ gb,
                              const void*  __restrict__ topn_p) {
    int wid  = threadIdx.x >> 5;
    int lane = threadIdx.x & 31;
    int t = blockIdx.x * (blockDim.x >> 5) + wid;
    if (t >= NTOK) return;

    float acc[NE];
#pragma unroll
    for (int e = 0; e < NE; e++) acc[e] = 0.f;

    const float* xr = x + (size_t)t * DIM;
    for (int d = lane; d < DIM; d += 32) {
        float xv = xr[d];
#pragma unroll
        for (int e = 0; e < NE; e++) acc[e] += xv * gw[d * NE + e];
    }
#pragma unroll
    for (int e = 0; e < NE; e++) {
        float v = acc[e];
#pragma unroll
        for (int o = 16; o; o >>= 1) v += __shfl_xor_sync(0xffffffffu, v, o);
        acc[e] = v;
    }

    if (lane == 0) {
        float logit[NE];
#pragma unroll
        for (int e = 0; e < NE; e++) logit[e] = acc[e] + gb[e];
        int tn = load_topn(topn_p);

        int sel[MAXK]; float sl[MAXK]; bool used[NE];
#pragma unroll
        for (int e = 0; e < NE; e++) used[e] = false;
        for (int k = 0; k < tn; k++) {
            int best = -1; float bv = -3.4e38f;
#pragma unroll
            for (int e = 0; e < NE; e++)
                if (!used[e] && logit[e] > bv) { bv = logit[e]; best = e; }
            used[best] = true; sel[k] = best; sl[k] = bv;
        }
        float m = sl[0], s = 0.f;
        for (int k = 0; k < tn; k++) { sl[k] = expf(sl[k] - m); s += sl[k]; }
        float inv = 1.f / s;
        for (int k = 0; k < tn; k++) {
            int e = sel[k];
            int slot = atomicAdd(&g_count[e], 1);
            g_tok [e * NTOK + slot] = t;
            g_slot[t * MAXK + k]    = e * SLAB + slot;
            g_wt  [t * MAXK + k]    = sl[k] * inv;
        }
    }
}

// ---------------- grouped GEMM: mma.sync tf32, cp.async 3-stage --------------
// A smem: row-major 128x32 floats, 16B-chunk swizzle: ch' = ch ^ (r&7)
// B smem: row-major 32x256 floats, 16B-chunk swizzle: ch' = ch ^ ((k&3)*2)
__global__ void __launch_bounds__(256, 1)
moe_gemm_tc(const float* __restrict__ x,
            const float* __restrict__ W,     // [NE][KDIM][DIM] row-major
            const float* __restrict__ bias,  // [NE][DIM]
            int mode) {
    int e = blockIdx.z;
    int cnt = g_count[e];
    int mbase = blockIdx.y * BM;
    if (mbase >= cnt) return;
    int nbase = blockIdx.x * BN;

    extern __shared__ char smem[];
    int tid = threadIdx.x;
    int wid = tid >> 5;
    int lane = tid & 31;
    int g = lane >> 2, tig = lane & 3;

    const float* Wb = W + (size_t)e * KDIM * DIM;
    const float* Bb = bias + (size_t)e * DIM;
    const float* Asrc = (mode == 1) ? g_h1 : g_h2;
    float* Out = (mode == 1) ? g_h2 : g_h1;

    const float** Arow = (const float**)(smem + SM_AROW);
    int* ArowSz = (int*)(smem + SM_ASZT);
    if (tid < BM) {
        int m = mbase + tid;
        const float* p = x;     // dummy valid pointer for zero-fill rows
        int sz = 0;
        if (m < cnt) {
            sz = 16;
            if (mode == 0) p = x + (size_t)g_tok[e * NTOK + m] * DIM;
            else           p = Asrc + ((size_t)e * SLAB + m) * DIM;
        }
        Arow[tid] = p;
        ArowSz[tid] = sz;
    }
    __syncthreads();

    uint32_t sA = smem_u32(smem + SM_A);
    uint32_t sB = smem_u32(smem + SM_B);

    // stage loader
    auto load_stage = [&](int slot, int kt) {
        int k0 = kt * BK;
        uint32_t as = sA + slot * ASZ;
        uint32_t bs = sB + slot * BSZ;
#pragma unroll
        for (int i = 0; i < 4; i++) {                  // A: 1024 chunks
            int idx = tid + i * 256;
            int r = idx >> 3, ch = idx & 7;
            uint32_t dst = as + r * 128 + ((ch ^ (r & 7)) << 4);
            cp_async16(dst, Arow[r] + k0 + ch * 4, ArowSz[r]);
        }
#pragma unroll
        for (int i = 0; i < 8; i++) {                  // B: 2048 chunks
            int idx = tid + i * 256;
            int r = idx >> 6, ch = idx & 63;
            uint32_t dst = bs + r * 1024 + ((ch ^ ((r & 3) << 1)) << 4);
            cp_async16(dst, Wb + (size_t)(k0 + r) * DIM + nbase + ch * 4, 16);
        }
    };

    // prologue
    load_stage(0, 0); CP_COMMIT();
    load_stage(1, 1); CP_COMMIT();

    // accumulators: warp tile 64x64
    int wm = (wid & 1) * 64;
    int wn = (wid >> 1) * 64;
    float acc[4][8][4];
#pragma unroll
    for (int i = 0; i < 4; i++)
#pragma unroll
        for (int j = 0; j < 8; j++)
#pragma unroll
            for (int q = 0; q < 4; q++) acc[i][j][q] = 0.f;

    for (int kt = 0; kt < KSTEPS; kt++) {
        int slot = kt % STAGES;
        CP_WAIT1();
        __syncthreads();
        if (kt + 2 < KSTEPS) load_stage((kt + 2) % STAGES, kt + 2);
        CP_COMMIT();

        uint32_t as = sA + slot * ASZ;
        uint32_t bs = sB + slot * BSZ;
#pragma unroll
        for (int ks = 0; ks < 4; ks++) {
            int c0 = ks * 8 + tig;
            int c2 = c0 + 4;
            uint32_t a[4][4];
#pragma unroll
            for (int mf = 0; mf < 4; mf++) {
                int r0 = wm + mf * 16 + g;
                uint32_t base0 = as + r0 * 128;
                uint32_t base1 = base0 + 8 * 128;
                uint32_t sw = (uint32_t)(g << 2);
                a[mf][0] = lds_cvt(base0 + (((uint32_t)c0 ^ sw) << 2));
                a[mf][1] = lds_cvt(base1 + (((uint32_t)c0 ^ sw) << 2));
                a[mf][2] = lds_cvt(base0 + (((uint32_t)c2 ^ sw) << 2));
                a[mf][3] = lds_cvt(base1 + (((uint32_t)c2 ^ sw) << 2));
            }
            int k0r = ks * 8 + tig;
            int k1r = k0r + 4;
            uint32_t swb = (uint32_t)((tig & 3) << 3);
            uint32_t b[8][2];
#pragma unroll
            for (int nf = 0; nf < 8; nf++) {
                uint32_t n = (uint32_t)(wn + nf * 8 + g);
                b[nf][0] = lds_cvt(bs + k0r * 1024 + ((n ^ swb) << 2));
                b[nf][1] = lds_cvt(bs + k1r * 1024 + ((n ^ swb) << 2));
            }
#pragma unroll
            for (int mf = 0; mf < 4; mf++)
#pragma unroll
                for (int nf = 0; nf < 8; nf++)
                    mma8(acc[mf][nf], a[mf][0], a[mf][1], a[mf][2], a[mf][3],
                         b[nf][0], b[nf][1]);
        }
    }

    // epilogue: bias + optional LeakyReLU, direct to gmem
    bool act = (mode != 2);
    float bw[8][2];
#pragma unroll
    for (int nf = 0; nf < 8; nf++) {
        int cc = nbase + wn + nf * 8 + 2 * tig;
        bw[nf][0] = Bb[cc];
        bw[nf][1] = Bb[cc + 1];
    }
    size_t rowbase = (size_t)e * SLAB + mbase + wm;
#pragma unroll
    for (int mf = 0; mf < 4; mf++) {
        float* p0 = Out + (rowbase + mf * 16 + g) * DIM + nbase + wn;
        float* p1 = p0 + 8 * DIM;
#pragma unroll
        for (int nf = 0; nf < 8; nf++) {
            float v0 = acc[mf][nf][0] + bw[nf][0];
            float v1 = acc[mf][nf][1] + bw[nf][1];
            float v2 = acc[mf][nf][2] + bw[nf][0];
            float v3 = acc[mf][nf][3] + bw[nf][1];
            if (act) {
                v0 = (v0 < 0.f) ? 0.01f * v0 : v0;
                v1 = (v1 < 0.f) ? 0.01f * v1 : v1;
                v2 = (v2 < 0.f) ? 0.01f * v2 : v2;
                v3 = (v3 < 0.f) ? 0.01f * v3 : v3;
            }
            int cc = nf * 8 + 2 * tig;
            *(float2*)(p0 + cc) = make_float2(v0, v1);
            *(float2*)(p1 + cc) = make_float2(v2, v3);
        }
    }
}

// ---------------- combine ------------------------------------------------------
__global__ void combine_kernel(float* __restrict__ out,
                               const void* __restrict__ topn_p) {
    int tn = load_topn(topn_p);
    size_t idx = (size_t)blockIdx.x * blockDim.x + threadIdx.x;
    if (idx >= (size_t)NTOK * DIM) return;
    int t = (int)(idx >> 10);
    int d = (int)(idx & (DIM - 1));
    float acc = 0.f;
    for (int k = 0; k < tn; k++) {
        int slot = g_slot[t * MAXK + k];
        acc += g_wt[t * MAXK + k] * g_h1[(size_t)slot * DIM + d];
    }
    out[idx] = acc;
}

// ---------------- launch ---------------------------------------------------------
extern "C" void kernel_launch(void* const* d_in, const int* in_sizes, int n_in,
                              void* d_out, int out_size) {
    const float* x   = (const float*)d_in[0];
    const float* gw  = (const float*)d_in[1];
    const float* gb  = (const float*)d_in[2];
    const float* w1  = (const float*)d_in[3];
    const float* b1  = (const float*)d_in[4];
    const float* w2  = (const float*)d_in[5];
    const float* b2  = (const float*)d_in[6];
    const float* w3  = (const float*)d_in[7];
    const float* b3  = (const float*)d_in[8];
    const void*  tp  = d_in[9];
    float* out = (float*)d_out;

    cudaFuncSetAttribute(moe_gemm_tc, cudaFuncAttributeMaxDynamicSharedMemorySize, SMEM_TOTAL);

    init_kernel<<<1, 32>>>();
    gating_kernel<<<NTOK / 8, 256>>>(x, gw, gb, tp);

    dim3 grid(DIM / BN, NTOK / BM, NE);    // (4, 64, 8)
    moe_gemm_tc<<<grid, 256, SMEM_TOTAL>>>(x, w1, b1, 0);
    moe_gemm_tc<<<grid, 256, SMEM_TOTAL>>>(x, w2, b2, 1);
    moe_gemm_tc<<<grid, 256, SMEM_TOTAL>>>(x, w3, b3, 2);

    combine_kernel<<<(NTOK * DIM + 255) / 256, 256>>>(out, tp);
}

// round 4
// speedup vs baseline: 3.7253x; 1.0028x over previous
#include <cuda_runtime.h>
#include <cstdint>

// Problem constants
#define NTOK  8192
#define DIM   1024
#define NE    8
#define MAXK  8
#define SLAB  8320
#define KDIM  1024

// GEMM tiling
#define BM 128
#define BN 256
#define BK 32
#define KSTEPS (KDIM / BK)   // 32
#define STAGES 4
#define ASZ (BM * BK * 4)    // 16384 B
#define BSZ (BK * BN * 4)    // 32768 B

// dynamic smem layout
#define SM_AROW 0
#define SM_ASZT 1024
#define SM_A    2048
#define SM_B    (SM_A + STAGES * ASZ)
#define SMEM_TOTAL (SM_B + STAGES * BSZ)   // 198656 B

// ---------------- scratch (device globals) ----------------------------------
__device__ int   g_count[NE];
__device__ int   g_tok [NE * NTOK];
__device__ int   g_slot[NTOK * MAXK];
__device__ float g_wt  [NTOK * MAXK];
__device__ float g_xr  [(size_t)NTOK * DIM];             // tf32-rounded x
__device__ float g_wr  [(size_t)3 * NE * KDIM * DIM];    // tf32-rounded weights
__device__ float g_h1  [(size_t)NE * SLAB * DIM];
__device__ float g_h2  [(size_t)NE * SLAB * DIM];

// ---------------- PTX helpers ------------------------------------------------
__device__ __forceinline__ uint32_t smem_u32(const void* p) {
    uint32_t a;
    asm("{ .reg .u64 t; cvta.to.shared.u64 t, %1; cvt.u32.u64 %0, t; }" : "=r"(a) : "l"(p));
    return a;
}

__device__ __forceinline__ void cp_async16(uint32_t dst, const void* src, uint32_t sz) {
    asm volatile("cp.async.cg.shared.global [%0], [%1], 16, %2;"
                 :: "r"(dst), "l"(src), "r"(sz) : "memory");
}
#define CP_COMMIT() asm volatile("cp.async.commit_group;" ::: "memory")
#define CP_WAIT2()  asm volatile("cp.async.wait_group 2;" ::: "memory")

__device__ __forceinline__ uint32_t lds32(uint32_t addr) {
    uint32_t v;
    asm volatile("ld.shared.b32 %0, [%1];" : "=r"(v) : "r"(addr));
    return v;
}

__device__ __forceinline__ float cvt_tf32(float f) {
    float r;
    asm("cvt.rna.tf32.f32 %0, %1;" : "=f"(r) : "f"(f));
    return r;
}

__device__ __forceinline__ void mma8(float* c, uint32_t a0, uint32_t a1, uint32_t a2,
                                     uint32_t a3, uint32_t b0, uint32_t b1) {
    asm volatile(
        "mma.sync.aligned.m16n8k8.row.col.f32.tf32.tf32.f32 "
        "{%0,%1,%2,%3}, {%4,%5,%6,%7}, {%8,%9}, {%0,%1,%2,%3};"
        : "+f"(c[0]), "+f"(c[1]), "+f"(c[2]), "+f"(c[3])
        : "r"(a0), "r"(a1), "r"(a2), "r"(a3), "r"(b0), "r"(b1));
}

// ---------------- misc helpers -----------------------------------------------
__device__ __forceinline__ int load_topn(const void* p) {
    int v = *(const int*)p;
    if (v >= 1 && v <= MAXK) return v;
    float f = *(const float*)p;
    int vi = (int)(f + 0.5f);
    if (vi >= 1 && vi <= MAXK) return vi;
    return 2;
}

__global__ void init_kernel() {
    if (threadIdx.x < NE) g_count[threadIdx.x] = 0;
}

// ---------------- tf32 pre-rounding (elementwise, float4) --------------------
__global__ void round_tf32_kernel(const float* __restrict__ src,
                                  float* __restrict__ dst, int n4) {
    int i = blockIdx.x * blockDim.x + threadIdx.x;
    if (i >= n4) return;
    float4 v = ((const float4*)src)[i];
    v.x = cvt_tf32(v.x); v.y = cvt_tf32(v.y);
    v.z = cvt_tf32(v.z); v.w = cvt_tf32(v.w);
    ((float4*)dst)[i] = v;
}

// ---------------- gating: one warp per token ---------------------------------
__global__ void gating_kernel(const float* __restrict__ x,
                              const float* __restrict__ gw,
                              const float* __restrict__ gb,
                              const void*  __restrict__ topn_p) {
    int wid  = threadIdx.x >> 5;
    int lane = threadIdx.x & 31;
    int t = blockIdx.x * (blockDim.x >> 5) + wid;
    if (t >= NTOK) return;

    float acc[NE];
#pragma unroll
    for (int e = 0; e < NE; e++) acc[e] = 0.f;

    const float* xr = x + (size_t)t * DIM;
    for (int d = lane; d < DIM; d += 32) {
        float xv = xr[d];
#pragma unroll
        for (int e = 0; e < NE; e++) acc[e] += xv * gw[d * NE + e];
    }
#pragma unroll
    for (int e = 0; e < NE; e++) {
        float v = acc[e];
#pragma unroll
        for (int o = 16; o; o >>= 1) v += __shfl_xor_sync(0xffffffffu, v, o);
        acc[e] = v;
    }

    if (lane == 0) {
        float logit[NE];
#pragma unroll
        for (int e = 0; e < NE; e++) logit[e] = acc[e] + gb[e];
        int tn = load_topn(topn_p);

        int sel[MAXK]; float sl[MAXK]; bool used[NE];
#pragma unroll
        for (int e = 0; e < NE; e++) used[e] = false;
        for (int k = 0; k < tn; k++) {
            int best = -1; float bv = -3.4e38f;
#pragma unroll
            for (int e = 0; e < NE; e++)
                if (!used[e] && logit[e] > bv) { bv = logit[e]; best = e; }
            used[best] = true; sel[k] = best; sl[k] = bv;
        }
        float m = sl[0], s = 0.f;
        for (int k = 0; k < tn; k++) { sl[k] = expf(sl[k] - m); s += sl[k]; }
        float inv = 1.f / s;
        for (int k = 0; k < tn; k++) {
            int e = sel[k];
            int slot = atomicAdd(&g_count[e], 1);
            g_tok [e * NTOK + slot] = t;
            g_slot[t * MAXK + k]    = e * SLAB + slot;
            g_wt  [t * MAXK + k]    = sl[k] * inv;
        }
    }
}

// ---------------- grouped GEMM: mma.sync tf32, cp.async 4-stage --------------
// Inputs are pre-rounded to tf32 values, so the mainloop is pure LDS + MMA.
__global__ void __launch_bounds__(256, 1)
moe_gemm_tc(const float* __restrict__ W,     // [NE][KDIM][DIM], pre-rounded
            const float* __restrict__ bias,  // [NE][DIM]
            int mode) {
    int e = blockIdx.z;
    int cnt = g_count[e];
    int mbase = blockIdx.y * BM;
    if (mbase >= cnt) return;
    int nbase = blockIdx.x * BN;

    extern __shared__ char smem[];
    int tid = threadIdx.x;
    int wid = tid >> 5;
    int lane = tid & 31;
    int g = lane >> 2, tig = lane & 3;

    const float* Wb = W + (size_t)e * KDIM * DIM;
    const float* Bb = bias + (size_t)e * DIM;
    const float* Asrc = (mode == 1) ? g_h1 : g_h2;
    float* Out = (mode == 1) ? g_h2 : g_h1;

    const float** Arow = (const float**)(smem + SM_AROW);
    int* ArowSz = (int*)(smem + SM_ASZT);
    if (tid < BM) {
        int m = mbase + tid;
        const float* p = g_xr;
        int sz = 0;
        if (m < cnt) {
            sz = 16;
            if (mode == 0) p = g_xr + (size_t)g_tok[e * NTOK + m] * DIM;
            else           p = Asrc + ((size_t)e * SLAB + m) * DIM;
        }
        Arow[tid] = p;
        ArowSz[tid] = sz;
    }
    __syncthreads();

    uint32_t sA = smem_u32(smem + SM_A);
    uint32_t sB = smem_u32(smem + SM_B);

    auto load_stage = [&](int slot, int kt) {
        int k0 = kt * BK;
        uint32_t as = sA + slot * ASZ;
        uint32_t bs = sB + slot * BSZ;
#pragma unroll
        for (int i = 0; i < 4; i++) {
            int idx = tid + i * 256;
            int r = idx >> 3, ch = idx & 7;
            uint32_t dst = as + r * 128 + ((ch ^ (r & 7)) << 4);
            cp_async16(dst, Arow[r] + k0 + ch * 4, ArowSz[r]);
        }
#pragma unroll
        for (int i = 0; i < 8; i++) {
            int idx = tid + i * 256;
            int r = idx >> 6, ch = idx & 63;
            uint32_t dst = bs + r * 1024 + ((ch ^ ((r & 3) << 1)) << 4);
            cp_async16(dst, Wb + (size_t)(k0 + r) * DIM + nbase + ch * 4, 16);
        }
    };

    // prologue: 3 stages in flight
    load_stage(0, 0); CP_COMMIT();
    load_stage(1, 1); CP_COMMIT();
    load_stage(2, 2); CP_COMMIT();

    int wm = (wid & 1) * 64;
    int wn = (wid >> 1) * 64;
    float acc[4][8][4];
#pragma unroll
    for (int i = 0; i < 4; i++)
#pragma unroll
        for (int j = 0; j < 8; j++)
#pragma unroll
            for (int q = 0; q < 4; q++) acc[i][j][q] = 0.f;

    for (int kt = 0; kt < KSTEPS; kt++) {
        int slot = kt & (STAGES - 1);
        CP_WAIT2();
        __syncthreads();
        if (kt + 3 < KSTEPS) load_stage((kt + 3) & (STAGES - 1), kt + 3);
        CP_COMMIT();

        uint32_t as = sA + slot * ASZ;
        uint32_t bs = sB + slot * BSZ;
#pragma unroll
        for (int ks = 0; ks < 4; ks++) {
            int c0 = ks * 8 + tig;
            int c2 = c0 + 4;
            uint32_t a[4][4];
#pragma unroll
            for (int mf = 0; mf < 4; mf++) {
                int r0 = wm + mf * 16 + g;
                uint32_t base0 = as + r0 * 128;
                uint32_t base1 = base0 + 8 * 128;
                uint32_t sw = (uint32_t)(g << 2);
                a[mf][0] = lds32(base0 + (((uint32_t)c0 ^ sw) << 2));
                a[mf][1] = lds32(base1 + (((uint32_t)c0 ^ sw) << 2));
                a[mf][2] = lds32(base0 + (((uint32_t)c2 ^ sw) << 2));
                a[mf][3] = lds32(base1 + (((uint32_t)c2 ^ sw) << 2));
            }
            int k0r = ks * 8 + tig;
            int k1r = k0r + 4;
            uint32_t swb = (uint32_t)((tig & 3) << 3);
            uint32_t b[8][2];
#pragma unroll
            for (int nf = 0; nf < 8; nf++) {
                uint32_t n = (uint32_t)(wn + nf * 8 + g);
                b[nf][0] = lds32(bs + k0r * 1024 + ((n ^ swb) << 2));
                b[nf][1] = lds32(bs + k1r * 1024 + ((n ^ swb) << 2));
            }
#pragma unroll
            for (int mf = 0; mf < 4; mf++)
#pragma unroll
                for (int nf = 0; nf < 8; nf++)
                    mma8(acc[mf][nf], a[mf][0], a[mf][1], a[mf][2], a[mf][3],
                         b[nf][0], b[nf][1]);
        }
    }

    // epilogue: bias + optional LeakyReLU (+ tf32 pre-round for next layer)
    bool act = (mode != 2);
    float bw[8][2];
#pragma unroll
    for (int nf = 0; nf < 8; nf++) {
        int cc = nbase + wn + nf * 8 + 2 * tig;
        bw[nf][0] = Bb[cc];
        bw[nf][1] = Bb[cc + 1];
    }
    size_t rowbase = (size_t)e * SLAB + mbase + wm;
#pragma unroll
    for (int mf = 0; mf < 4; mf++) {
        float* p0 = Out + (rowbase + mf * 16 + g) * DIM + nbase + wn;
        float* p1 = p0 + 8 * DIM;
#pragma unroll
        for (int nf = 0; nf < 8; nf++) {
            float v0 = acc[mf][nf][0] + bw[nf][0];
            float v1 = acc[mf][nf][1] + bw[nf][1];
            float v2 = acc[mf][nf][2] + bw[nf][0];
            float v3 = acc[mf][nf][3] + bw[nf][1];
            if (act) {
                v0 = (v0 < 0.f) ? 0.01f * v0 : v0;
                v1 = (v1 < 0.f) ? 0.01f * v1 : v1;
                v2 = (v2 < 0.f) ? 0.01f * v2 : v2;
                v3 = (v3 < 0.f) ? 0.01f * v3 : v3;
                v0 = cvt_tf32(v0); v1 = cvt_tf32(v1);
                v2 = cvt_tf32(v2); v3 = cvt_tf32(v3);
            }
            int cc = nf * 8 + 2 * tig;
            *(float2*)(p0 + cc) = make_float2(v0, v1);
            *(float2*)(p1 + cc) = make_float2(v2, v3);
        }
    }
}

// ---------------- combine ------------------------------------------------------
__global__ void combine_kernel(float* __restrict__ out,
                               const void* __restrict__ topn_p) {
    int tn = load_topn(topn_p);
    size_t idx = (size_t)blockIdx.x * blockDim.x + threadIdx.x;
    if (idx >= (size_t)NTOK * DIM) return;
    int t = (int)(idx >> 10);
    int d = (int)(idx & (DIM - 1));
    float acc = 0.f;
    for (int k = 0; k < tn; k++) {
        int slot = g_slot[t * MAXK + k];
        acc += g_wt[t * MAXK + k] * g_h1[(size_t)slot * DIM + d];
    }
    out[idx] = acc;
}

// ---------------- launch ---------------------------------------------------------
extern "C" void kernel_launch(void* const* d_in, const int* in_sizes, int n_in,
                              void* d_out, int out_size) {
    const float* x   = (const float*)d_in[0];
    const float* gw  = (const float*)d_in[1];
    const float* gb  = (const float*)d_in[2];
    const float* w1  = (const float*)d_in[3];
    const float* b1  = (const float*)d_in[4];
    const float* w2  = (const float*)d_in[5];
    const float* b2  = (const float*)d_in[6];
    const float* w3  = (const float*)d_in[7];
    const float* b3  = (const float*)d_in[8];
    const void*  tp  = d_in[9];
    float* out = (float*)d_out;

    cudaFuncSetAttribute(moe_gemm_tc, cudaFuncAttributeMaxDynamicSharedMemorySize, SMEM_TOTAL);

    float *xr, *wr;
    cudaGetSymbolAddress((void**)&xr, g_xr);
    cudaGetSymbolAddress((void**)&wr, g_wr);
    size_t lsz = (size_t)NE * KDIM * DIM;

    init_kernel<<<1, 32>>>();
    gating_kernel<<<NTOK / 8, 256>>>(x, gw, gb, tp);

    // tf32 pre-rounding
    int n4x = NTOK * DIM / 4;
    int n4w = (int)(lsz / 4);
    round_tf32_kernel<<<(n4x + 255) / 256, 256>>>(x,  xr,            n4x);
    round_tf32_kernel<<<(n4w + 255) / 256, 256>>>(w1, wr + 0 * lsz,  n4w);
    round_tf32_kernel<<<(n4w + 255) / 256, 256>>>(w2, wr + 1 * lsz,  n4w);
    round_tf32_kernel<<<(n4w + 255) / 256, 256>>>(w3, wr + 2 * lsz,  n4w);

    dim3 grid(DIM / BN, NTOK / BM, NE);    // (4, 64, 8)
    moe_gemm_tc<<<grid, 256, SMEM_TOTAL>>>(wr + 0 * lsz, b1, 0);
    moe_gemm_tc<<<grid, 256, SMEM_TOTAL>>>(wr + 1 * lsz, b2, 1);
    moe_gemm_tc<<<grid, 256, SMEM_TOTAL>>>(wr + 2 * lsz, b3, 2);

    combine_kernel<<<(NTOK * DIM + 255) / 256, 256>>>(out, tp);
}

// round 5
// speedup vs baseline: 3.8157x; 1.0243x over previous
#include <cuda_runtime.h>
#include <cstdint>

// Problem constants
#define NTOK  8192
#define DIM   1024
#define NE    8
#define MAXK  8
#define SLAB  8320
#define KDIM  1024

// GEMM tiling
#define BM 128
#define BN 256
#define BK 32
#define KSTEPS (KDIM / BK)   // 32
#define STAGES 4
#define NTHREADS 512
#define ASZ (BM * BK * 4)    // 16384 B
#define BSZ (BK * BN * 4)    // 32768 B

// dynamic smem layout
#define SM_AROW 0
#define SM_ASZT 1024
#define SM_A    2048
#define SM_B    (SM_A + STAGES * ASZ)
#define SMEM_TOTAL (SM_B + STAGES * BSZ)   // 198656 B

// ---------------- scratch (device globals) ----------------------------------
__device__ int   g_count[NE];
__device__ int   g_tok [NE * NTOK];
__device__ int   g_slot[NTOK * MAXK];
__device__ float g_wt  [NTOK * MAXK];
__device__ float g_xr  [(size_t)NTOK * DIM];             // tf32-rounded x
__device__ float g_wr  [(size_t)3 * NE * KDIM * DIM];    // tf32-rounded weights
__device__ float g_h1  [(size_t)NE * SLAB * DIM];
__device__ float g_h2  [(size_t)NE * SLAB * DIM];

// ---------------- PTX helpers ------------------------------------------------
__device__ __forceinline__ uint32_t smem_u32(const void* p) {
    uint32_t a;
    asm("{ .reg .u64 t; cvta.to.shared.u64 t, %1; cvt.u32.u64 %0, t; }" : "=r"(a) : "l"(p));
    return a;
}

__device__ __forceinline__ void cp_async16(uint32_t dst, const void* src, uint32_t sz) {
    asm volatile("cp.async.cg.shared.global [%0], [%1], 16, %2;"
                 :: "r"(dst), "l"(src), "r"(sz) : "memory");
}
#define CP_COMMIT() asm volatile("cp.async.commit_group;" ::: "memory")
#define CP_WAIT2()  asm volatile("cp.async.wait_group 2;" ::: "memory")

__device__ __forceinline__ uint32_t lds32(uint32_t addr) {
    uint32_t v;
    asm volatile("ld.shared.b32 %0, [%1];" : "=r"(v) : "r"(addr));
    return v;
}

__device__ __forceinline__ float cvt_tf32(float f) {
    float r;
    asm("cvt.rna.tf32.f32 %0, %1;" : "=f"(r) : "f"(f));
    return r;
}

__device__ __forceinline__ void mma8(float* c, uint32_t a0, uint32_t a1, uint32_t a2,
                                     uint32_t a3, uint32_t b0, uint32_t b1) {
    asm volatile(
        "mma.sync.aligned.m16n8k8.row.col.f32.tf32.tf32.f32 "
        "{%0,%1,%2,%3}, {%4,%5,%6,%7}, {%8,%9}, {%0,%1,%2,%3};"
        : "+f"(c[0]), "+f"(c[1]), "+f"(c[2]), "+f"(c[3])
        : "r"(a0), "r"(a1), "r"(a2), "r"(a3), "r"(b0), "r"(b1));
}

// ---------------- misc helpers -----------------------------------------------
__device__ __forceinline__ int load_topn(const void* p) {
    int v = *(const int*)p;
    if (v >= 1 && v <= MAXK) return v;
    float f = *(const float*)p;
    int vi = (int)(f + 0.5f);
    if (vi >= 1 && vi <= MAXK) return vi;
    return 2;
}

__global__ void init_kernel() {
    if (threadIdx.x < NE) g_count[threadIdx.x] = 0;
}

// ---------------- tf32 pre-rounding ------------------------------------------
__global__ void round_tf32_kernel(const float* __restrict__ src,
                                  float* __restrict__ dst, int n4) {
    int i = blockIdx.x * blockDim.x + threadIdx.x;
    if (i >= n4) return;
    float4 v = ((const float4*)src)[i];
    v.x = cvt_tf32(v.x); v.y = cvt_tf32(v.y);
    v.z = cvt_tf32(v.z); v.w = cvt_tf32(v.w);
    ((float4*)dst)[i] = v;
}

// ---------------- gating: one warp per token ---------------------------------
__global__ void gating_kernel(const float* __restrict__ x,
                              const float* __restrict__ gw,
                              const float* __restrict__ gb,
                              const void*  __restrict__ topn_p) {
    int wid  = threadIdx.x >> 5;
    int lane = threadIdx.x & 31;
    int t = blockIdx.x * (blockDim.x >> 5) + wid;
    if (t >= NTOK) return;

    float acc[NE];
#pragma unroll
    for (int e = 0; e < NE; e++) acc[e] = 0.f;

    const float* xr = x + (size_t)t * DIM;
    for (int d = lane; d < DIM; d += 32) {
        float xv = xr[d];
#pragma unroll
        for (int e = 0; e < NE; e++) acc[e] += xv * gw[d * NE + e];
    }
#pragma unroll
    for (int e = 0; e < NE; e++) {
        float v = acc[e];
#pragma unroll
        for (int o = 16; o; o >>= 1) v += __shfl_xor_sync(0xffffffffu, v, o);
        acc[e] = v;
    }

    if (lane == 0) {
        float logit[NE];
#pragma unroll
        for (int e = 0; e < NE; e++) logit[e] = acc[e] + gb[e];
        int tn = load_topn(topn_p);

        int sel[MAXK]; float sl[MAXK]; bool used[NE];
#pragma unroll
        for (int e = 0; e < NE; e++) used[e] = false;
        for (int k = 0; k < tn; k++) {
            int best = -1; float bv = -3.4e38f;
#pragma unroll
            for (int e = 0; e < NE; e++)
                if (!used[e] && logit[e] > bv) { bv = logit[e]; best = e; }
            used[best] = true; sel[k] = best; sl[k] = bv;
        }
        float m = sl[0], s = 0.f;
        for (int k = 0; k < tn; k++) { sl[k] = expf(sl[k] - m); s += sl[k]; }
        float inv = 1.f / s;
        for (int k = 0; k < tn; k++) {
            int e = sel[k];
            int slot = atomicAdd(&g_count[e], 1);
            g_tok [e * NTOK + slot] = t;
            g_slot[t * MAXK + k]    = e * SLAB + slot;
            g_wt  [t * MAXK + k]    = sl[k] * inv;
        }
    }
}

// ---------------- grouped GEMM: mma.sync tf32, 512 threads, 16 warps ---------
__global__ void __launch_bounds__(NTHREADS, 1)
moe_gemm_tc(const float* __restrict__ W,     // [NE][KDIM][DIM], pre-rounded
            const float* __restrict__ bias,  // [NE][DIM]
            int mode) {
    int e = blockIdx.z;
    int cnt = g_count[e];
    int mbase = blockIdx.y * BM;
    if (mbase >= cnt) return;
    int nbase = blockIdx.x * BN;

    extern __shared__ char smem[];
    int tid = threadIdx.x;
    int wid = tid >> 5;
    int lane = tid & 31;
    int g = lane >> 2, tig = lane & 3;

    const float* Wb = W + (size_t)e * KDIM * DIM;
    const float* Bb = bias + (size_t)e * DIM;
    const float* Asrc = (mode == 1) ? g_h1 : g_h2;
    float* Out = (mode == 1) ? g_h2 : g_h1;

    const float** Arow = (const float**)(smem + SM_AROW);
    int* ArowSz = (int*)(smem + SM_ASZT);
    if (tid < BM) {
        int m = mbase + tid;
        const float* p = g_xr;
        int sz = 0;
        if (m < cnt) {
            sz = 16;
            if (mode == 0) p = g_xr + (size_t)g_tok[e * NTOK + m] * DIM;
            else           p = Asrc + ((size_t)e * SLAB + m) * DIM;
        }
        Arow[tid] = p;
        ArowSz[tid] = sz;
    }
    __syncthreads();

    uint32_t sA = smem_u32(smem + SM_A);
    uint32_t sB = smem_u32(smem + SM_B);

    auto load_stage = [&](int slot, int kt) {
        int k0 = kt * BK;
        uint32_t as = sA + slot * ASZ;
        uint32_t bs = sB + slot * BSZ;
#pragma unroll
        for (int i = 0; i < 2; i++) {                 // A: 1024 chunks
            int idx = tid + i * NTHREADS;
            int r = idx >> 3, ch = idx & 7;
            uint32_t dst = as + r * 128 + ((ch ^ (r & 7)) << 4);
            cp_async16(dst, Arow[r] + k0 + ch * 4, ArowSz[r]);
        }
#pragma unroll
        for (int i = 0; i < 4; i++) {                 // B: 2048 chunks
            int idx = tid + i * NTHREADS;
            int r = idx >> 6, ch = idx & 63;
            uint32_t dst = bs + r * 1024 + ((ch ^ ((r & 3) << 1)) << 4);
            cp_async16(dst, Wb + (size_t)(k0 + r) * DIM + nbase + ch * 4, 16);
        }
    };

    // prologue: 3 stages in flight
    load_stage(0, 0); CP_COMMIT();
    load_stage(1, 1); CP_COMMIT();
    load_stage(2, 2); CP_COMMIT();

    // warp tile 64x32: 2 warp-rows x 8 warp-cols
    int wm = (wid & 1) * 64;
    int wn = (wid >> 1) * 32;

    // precomputed fragment offsets
    uint32_t swA = (uint32_t)(g << 2);
    uint32_t colA[4][2];
#pragma unroll
    for (int ks = 0; ks < 4; ks++) {
        colA[ks][0] = (((uint32_t)(ks * 8 + tig)) ^ swA) << 2;
        colA[ks][1] = (((uint32_t)(ks * 8 + tig + 4)) ^ swA) << 2;
    }
    uint32_t colB[4];
#pragma unroll
    for (int nf = 0; nf < 4; nf++)
        colB[nf] = (((uint32_t)(wn + nf * 8 + g)) ^ ((uint32_t)tig << 3)) << 2;

    float acc[4][4][4];
#pragma unroll
    for (int i = 0; i < 4; i++)
#pragma unroll
        for (int j = 0; j < 4; j++)
#pragma unroll
            for (int q = 0; q < 4; q++) acc[i][j][q] = 0.f;

    for (int kt = 0; kt < KSTEPS; kt++) {
        int slot = kt & (STAGES - 1);
        CP_WAIT2();
        __syncthreads();
        if (kt + 3 < KSTEPS) load_stage((kt + 3) & (STAGES - 1), kt + 3);
        CP_COMMIT();

        uint32_t as = sA + slot * ASZ + (uint32_t)(wm + g) * 128;
        uint32_t bs = sB + slot * BSZ + (uint32_t)(tig * 1024);
#pragma unroll
        for (int ks = 0; ks < 4; ks++) {
            uint32_t brow0 = bs + (uint32_t)(ks * 8) * 1024;
            uint32_t brow1 = brow0 + 4096;
            uint32_t b[4][2];
#pragma unroll
            for (int nf = 0; nf < 4; nf++) {
                b[nf][0] = lds32(brow0 + colB[nf]);
                b[nf][1] = lds32(brow1 + colB[nf]);
            }
            uint32_t a[4][4];
#pragma unroll
            for (int mf = 0; mf < 4; mf++) {
                uint32_t base0 = as + (uint32_t)(mf * 16) * 128;
                uint32_t base1 = base0 + 8 * 128;
                a[mf][0] = lds32(base0 + colA[ks][0]);
                a[mf][1] = lds32(base1 + colA[ks][0]);
                a[mf][2] = lds32(base0 + colA[ks][1]);
                a[mf][3] = lds32(base1 + colA[ks][1]);
            }
#pragma unroll
            for (int mf = 0; mf < 4; mf++)
#pragma unroll
                for (int nf = 0; nf < 4; nf++)
                    mma8(acc[mf][nf], a[mf][0], a[mf][1], a[mf][2], a[mf][3],
                         b[nf][0], b[nf][1]);
        }
    }

    // epilogue: bias + optional LeakyReLU (+ tf32 pre-round for next layer)
    bool act = (mode != 2);
    float bw[4][2];
#pragma unroll
    for (int nf = 0; nf < 4; nf++) {
        int cc = nbase + wn + nf * 8 + 2 * tig;
        bw[nf][0] = Bb[cc];
        bw[nf][1] = Bb[cc + 1];
    }
    size_t rowbase = (size_t)e * SLAB + mbase + wm;
#pragma unroll
    for (int mf = 0; mf < 4; mf++) {
        float* p0 = Out + (rowbase + mf * 16 + g) * DIM + nbase + wn;
        float* p1 = p0 + 8 * DIM;
#pragma unroll
        for (int nf = 0; nf < 4; nf++) {
            float v0 = acc[mf][nf][0] + bw[nf][0];
            float v1 = acc[mf][nf][1] + bw[nf][1];
            float v2 = acc[mf][nf][2] + bw[nf][0];
            float v3 = acc[mf][nf][3] + bw[nf][1];
            if (act) {
                v0 = (v0 < 0.f) ? 0.01f * v0 : v0;
                v1 = (v1 < 0.f) ? 0.01f * v1 : v1;
                v2 = (v2 < 0.f) ? 0.01f * v2 : v2;
                v3 = (v3 < 0.f) ? 0.01f * v3 : v3;
                v0 = cvt_tf32(v0); v1 = cvt_tf32(v1);
                v2 = cvt_tf32(v2); v3 = cvt_tf32(v3);
            }
            int cc = nf * 8 + 2 * tig;
            *(float2*)(p0 + cc) = make_float2(v0, v1);
            *(float2*)(p1 + cc) = make_float2(v2, v3);
        }
    }
}

// ---------------- combine ------------------------------------------------------
__global__ void combine_kernel(float* __restrict__ out,
                               const void* __restrict__ topn_p) {
    int tn = load_topn(topn_p);
    size_t idx = (size_t)blockIdx.x * blockDim.x + threadIdx.x;
    if (idx >= (size_t)NTOK * DIM) return;
    int t = (int)(idx >> 10);
    int d = (int)(idx & (DIM - 1));
    float acc = 0.f;
    for (int k = 0; k < tn; k++) {
        int slot = g_slot[t * MAXK + k];
        acc += g_wt[t * MAXK + k] * g_h1[(size_t)slot * DIM + d];
    }
    out[idx] = acc;
}

// ---------------- launch ---------------------------------------------------------
extern "C" void kernel_launch(void* const* d_in, const int* in_sizes, int n_in,
                              void* d_out, int out_size) {
    const float* x   = (const float*)d_in[0];
    const float* gw  = (const float*)d_in[1];
    const float* gb  = (const float*)d_in[2];
    const float* w1  = (const float*)d_in[3];
    const float* b1  = (const float*)d_in[4];
    const float* w2  = (const float*)d_in[5];
    const float* b2  = (const float*)d_in[6];
    const float* w3  = (const float*)d_in[7];
    const float* b3  = (const float*)d_in[8];
    const void*  tp  = d_in[9];
    float* out = (float*)d_out;

    cudaFuncSetAttribute(moe_gemm_tc, cudaFuncAttributeMaxDynamicSharedMemorySize, SMEM_TOTAL);

    float *xr, *wr;
    cudaGetSymbolAddress((void**)&xr, g_xr);
    cudaGetSymbolAddress((void**)&wr, g_wr);
    size_t lsz = (size_t)NE * KDIM * DIM;

    init_kernel<<<1, 32>>>();
    gating_kernel<<<NTOK / 8, 256>>>(x, gw, gb, tp);

    int n4x = NTOK * DIM / 4;
    int n4w = (int)(lsz / 4);
    round_tf32_kernel<<<(n4x + 255) / 256, 256>>>(x,  xr,            n4x);
    round_tf32_kernel<<<(n4w + 255) / 256, 256>>>(w1, wr + 0 * lsz,  n4w);
    round_tf32_kernel<<<(n4w + 255) / 256, 256>>>(w2, wr + 1 * lsz,  n4w);
    round_tf32_kernel<<<(n4w + 255) / 256, 256>>>(w3, wr + 2 * lsz,  n4w);

    dim3 grid(DIM / BN, NTOK / BM, NE);    // (4, 64, 8)
    moe_gemm_tc<<<grid, NTHREADS, SMEM_TOTAL>>>(wr + 0 * lsz, b1, 0);
    moe_gemm_tc<<<grid, NTHREADS, SMEM_TOTAL>>>(wr + 1 * lsz, b2, 1);
    moe_gemm_tc<<<grid, NTHREADS, SMEM_TOTAL>>>(wr + 2 * lsz, b3, 2);

    combine_kernel<<<(NTOK * DIM + 255) / 256, 256>>>(out, tp);
}

// round 6
// speedup vs baseline: 6.4060x; 1.6788x over previous
#include <cuda_runtime.h>
#include <cuda_fp16.h>
#include <cstdint>

// Problem constants
#define NTOK  8192
#define DIM   1024
#define NE    8
#define MAXK  8
#define SLAB  8320
#define KDIM  1024

// GEMM tiling (fp16 path)
#define BM 128
#define BN 256
#define BK 64
#define KSTEPS (KDIM / BK)   // 16
#define STAGES 4
#define NTHREADS 512
#define ASZ (BM * BK * 2)    // 16384 B
#define BSZ (BK * BN * 2)    // 32768 B

// dynamic smem layout
#define SM_AROW 0
#define SM_ASZT 1024
#define SM_A    2048
#define SM_B    (SM_A + STAGES * ASZ)
#define SMEM_TOTAL (SM_B + STAGES * BSZ)   // 198656 B

// ---------------- scratch (device globals) ----------------------------------
__device__ int    g_count[NE];
__device__ int    g_tok [NE * NTOK];
__device__ int    g_slot[NTOK * MAXK];
__device__ float  g_wt  [NTOK * MAXK];
__device__ __half g_xh  [(size_t)NTOK * DIM];             // fp16 x
__device__ __half g_wh  [(size_t)3 * NE * KDIM * DIM];    // fp16 weights
__device__ __half g_h1h [(size_t)NE * SLAB * DIM];        // fp16 layer1 out
__device__ __half g_h2h [(size_t)NE * SLAB * DIM];        // fp16 layer2 out
__device__ float  g_eo  [(size_t)NE * SLAB * DIM];        // fp32 expert out

// ---------------- PTX helpers ------------------------------------------------
__device__ __forceinline__ uint32_t smem_u32(const void* p) {
    uint32_t a;
    asm("{ .reg .u64 t; cvta.to.shared.u64 t, %1; cvt.u32.u64 %0, t; }" : "=r"(a) : "l"(p));
    return a;
}

__device__ __forceinline__ void cp_async16(uint32_t dst, const void* src, uint32_t sz) {
    asm volatile("cp.async.cg.shared.global [%0], [%1], 16, %2;"
                 :: "r"(dst), "l"(src), "r"(sz) : "memory");
}
#define CP_COMMIT() asm volatile("cp.async.commit_group;" ::: "memory")
#define CP_WAIT2()  asm volatile("cp.async.wait_group 2;" ::: "memory")

__device__ __forceinline__ void ldsm4(uint32_t* r, uint32_t addr) {
    asm volatile("ldmatrix.sync.aligned.m8n8.x4.shared.b16 {%0,%1,%2,%3}, [%4];"
                 : "=r"(r[0]), "=r"(r[1]), "=r"(r[2]), "=r"(r[3]) : "r"(addr));
}
__device__ __forceinline__ void ldsm4t(uint32_t* r, uint32_t addr) {
    asm volatile("ldmatrix.sync.aligned.m8n8.x4.trans.shared.b16 {%0,%1,%2,%3}, [%4];"
                 : "=r"(r[0]), "=r"(r[1]), "=r"(r[2]), "=r"(r[3]) : "r"(addr));
}

__device__ __forceinline__ void mma16(float* c, const uint32_t* a, uint32_t b0, uint32_t b1) {
    asm volatile(
        "mma.sync.aligned.m16n8k16.row.col.f32.f16.f16.f32 "
        "{%0,%1,%2,%3}, {%4,%5,%6,%7}, {%8,%9}, {%0,%1,%2,%3};"
        : "+f"(c[0]), "+f"(c[1]), "+f"(c[2]), "+f"(c[3])
        : "r"(a[0]), "r"(a[1]), "r"(a[2]), "r"(a[3]), "r"(b0), "r"(b1));
}

// ---------------- misc helpers -----------------------------------------------
__device__ __forceinline__ int load_topn(const void* p) {
    int v = *(const int*)p;
    if (v >= 1 && v <= MAXK) return v;
    float f = *(const float*)p;
    int vi = (int)(f + 0.5f);
    if (vi >= 1 && vi <= MAXK) return vi;
    return 2;
}

__global__ void init_kernel() {
    if (threadIdx.x < NE) g_count[threadIdx.x] = 0;
}

// ---------------- fp32 -> fp16 convert ----------------------------------------
__global__ void f2h_kernel(const float* __restrict__ src,
                           __half* __restrict__ dst, int n4) {
    int i = blockIdx.x * blockDim.x + threadIdx.x;
    if (i >= n4) return;
    float4 v = ((const float4*)src)[i];
    __half2 h0 = __floats2half2_rn(v.x, v.y);
    __half2 h1 = __floats2half2_rn(v.z, v.w);
    uint32_t u0 = *(uint32_t*)&h0, u1 = *(uint32_t*)&h1;
    ((uint2*)dst)[i] = make_uint2(u0, u1);
}

// ---------------- gating: one warp per token ---------------------------------
__global__ void gating_kernel(const float* __restrict__ x,
                              const float* __restrict__ gw,
                              const float* __restrict__ gb,
                              const void*  __restrict__ topn_p) {
    int wid  = threadIdx.x >> 5;
    int lane = threadIdx.x & 31;
    int t = blockIdx.x * (blockDim.x >> 5) + wid;
    if (t >= NTOK) return;

    float acc[NE];
#pragma unroll
    for (int e = 0; e < NE; e++) acc[e] = 0.f;

    const float* xr = x + (size_t)t * DIM;
    for (int d = lane; d < DIM; d += 32) {
        float xv = xr[d];
#pragma unroll
        for (int e = 0; e < NE; e++) acc[e] += xv * gw[d * NE + e];
    }
#pragma unroll
    for (int e = 0; e < NE; e++) {
        float v = acc[e];
#pragma unroll
        for (int o = 16; o; o >>= 1) v += __shfl_xor_sync(0xffffffffu, v, o);
        acc[e] = v;
    }

    if (lane == 0) {
        float logit[NE];
#pragma unroll
        for (int e = 0; e < NE; e++) logit[e] = acc[e] + gb[e];
        int tn = load_topn(topn_p);

        int sel[MAXK]; float sl[MAXK]; bool used[NE];
#pragma unroll
        for (int e = 0; e < NE; e++) used[e] = false;
        for (int k = 0; k < tn; k++) {
            int best = -1; float bv = -3.4e38f;
#pragma unroll
            for (int e = 0; e < NE; e++)
                if (!used[e] && logit[e] > bv) { bv = logit[e]; best = e; }
            used[best] = true; sel[k] = best; sl[k] = bv;
        }
        float m = sl[0], s = 0.f;
        for (int k = 0; k < tn; k++) { sl[k] = expf(sl[k] - m); s += sl[k]; }
        float inv = 1.f / s;
        for (int k = 0; k < tn; k++) {
            int e = sel[k];
            int slot = atomicAdd(&g_count[e], 1);
            g_tok [e * NTOK + slot] = t;
            g_slot[t * MAXK + k]    = e * SLAB + slot;
            g_wt  [t * MAXK + k]    = sl[k] * inv;
        }
    }
}

// ---------------- grouped GEMM: fp16 mma.sync m16n8k16 + ldmatrix ------------
// A smem: 128 rows x 64 halves (128B rows), chunk swizzle ch^=r&7
// B smem: 64 k-rows x 256 halves (512B rows), chunk swizzle ch^=k&7
__global__ void __launch_bounds__(NTHREADS, 1)
moe_gemm_tc(const __half* __restrict__ W,    // [NE][KDIM][DIM] fp16
            const float* __restrict__ bias,  // [NE][DIM] fp32
            int mode) {
    int e = blockIdx.z;
    int cnt = g_count[e];
    int mbase = blockIdx.y * BM;
    if (mbase >= cnt) return;
    int nbase = blockIdx.x * BN;

    extern __shared__ char smem[];
    int tid = threadIdx.x;
    int wid = tid >> 5;
    int lane = tid & 31;
    int g = lane >> 2, tig = lane & 3;

    const __half* Wb = W + (size_t)e * KDIM * DIM;
    const float*  Bb = bias + (size_t)e * DIM;
    const __half* Asrc = (mode == 1) ? g_h1h : g_h2h;

    const __half** Arow = (const __half**)(smem + SM_AROW);
    int* ArowSz = (int*)(smem + SM_ASZT);
    if (tid < BM) {
        int m = mbase + tid;
        const __half* p = g_xh;
        int sz = 0;
        if (m < cnt) {
            sz = 16;
            if (mode == 0) p = g_xh + (size_t)g_tok[e * NTOK + m] * DIM;
            else           p = Asrc + ((size_t)e * SLAB + m) * DIM;
        }
        Arow[tid] = p;
        ArowSz[tid] = sz;
    }
    __syncthreads();

    uint32_t sA = smem_u32(smem + SM_A);
    uint32_t sB = smem_u32(smem + SM_B);

    auto load_stage = [&](int slot, int kt) {
        int k0 = kt * BK;
        uint32_t as = sA + slot * ASZ;
        uint32_t bs = sB + slot * BSZ;
#pragma unroll
        for (int i = 0; i < 2; i++) {                 // A: 1024 chunks of 16B
            int idx = tid + i * NTHREADS;
            int r = idx >> 3, ch = idx & 7;
            uint32_t dst = as + r * 128 + ((ch ^ (r & 7)) << 4);
            cp_async16(dst, Arow[r] + k0 + ch * 8, ArowSz[r]);
        }
#pragma unroll
        for (int i = 0; i < 4; i++) {                 // B: 2048 chunks of 16B
            int idx = tid + i * NTHREADS;
            int r = idx >> 5, ch = idx & 31;
            uint32_t dst = bs + r * 512 + ((ch ^ (r & 7)) << 4);
            cp_async16(dst, Wb + (size_t)(k0 + r) * DIM + nbase + ch * 8, 16);
        }
    };

    // prologue: 3 stages in flight
    load_stage(0, 0); CP_COMMIT();
    load_stage(1, 1); CP_COMMIT();
    load_stage(2, 2); CP_COMMIT();

    // warp tile 64x32
    int wm = (wid & 1) * 64;
    int wn = (wid >> 1) * 32;

    // precomputed ldmatrix offsets
    int l15 = lane & 15, hi = lane >> 4, l7 = lane & 7;
    uint32_t aRowOff = (uint32_t)(wm + l15) * 128;       // + mf*2048 + swcA[ks]
    uint32_t swcA[4];
#pragma unroll
    for (int ks = 0; ks < 4; ks++)
        swcA[ks] = (uint32_t)(((ks * 2 + hi) ^ l7) << 4);
    uint32_t bRowOff = (uint32_t)l15 * 512;              // + ks*8192 + cBn[nt]
    int nch = (wn >> 3);
    uint32_t cBn[2];
#pragma unroll
    for (int nt = 0; nt < 2; nt++)
        cBn[nt] = (uint32_t)((((nch + nt * 2) + hi) ^ l7) << 4);

    float acc[4][4][4];
#pragma unroll
    for (int i = 0; i < 4; i++)
#pragma unroll
        for (int j = 0; j < 4; j++)
#pragma unroll
            for (int q = 0; q < 4; q++) acc[i][j][q] = 0.f;

    for (int kt = 0; kt < KSTEPS; kt++) {
        int slot = kt & (STAGES - 1);
        CP_WAIT2();
        __syncthreads();
        if (kt + 3 < KSTEPS) load_stage((kt + 3) & (STAGES - 1), kt + 3);
        CP_COMMIT();

        uint32_t as = sA + slot * ASZ + aRowOff;
        uint32_t bs = sB + slot * BSZ + bRowOff;
#pragma unroll
        for (int ks = 0; ks < 4; ks++) {
            uint32_t a[4][4];
#pragma unroll
            for (int mf = 0; mf < 4; mf++)
                ldsm4(a[mf], as + mf * 2048 + swcA[ks]);
            uint32_t b[2][4];
            uint32_t bk = bs + ks * 8192;
            ldsm4t(b[0], bk + cBn[0]);
            ldsm4t(b[1], bk + cBn[1]);
#pragma unroll
            for (int mf = 0; mf < 4; mf++) {
                mma16(acc[mf][0], a[mf], b[0][0], b[0][1]);
                mma16(acc[mf][1], a[mf], b[0][2], b[0][3]);
                mma16(acc[mf][2], a[mf], b[1][0], b[1][1]);
                mma16(acc[mf][3], a[mf], b[1][2], b[1][3]);
            }
        }
    }

    // epilogue: bias + optional LeakyReLU; fp16 out for modes 0/1, fp32 for mode 2
    float bw[4][2];
#pragma unroll
    for (int nf = 0; nf < 4; nf++) {
        int cc = nbase + wn + nf * 8 + 2 * tig;
        bw[nf][0] = Bb[cc];
        bw[nf][1] = Bb[cc + 1];
    }
    size_t rowbase = (size_t)e * SLAB + mbase + wm;
    if (mode != 2) {
        __half* OutH = (mode == 1) ? g_h2h : g_h1h;
#pragma unroll
        for (int mf = 0; mf < 4; mf++) {
            __half* p0 = OutH + (rowbase + mf * 16 + g) * DIM + nbase + wn;
            __half* p1 = p0 + 8 * DIM;
#pragma unroll
            for (int nf = 0; nf < 4; nf++) {
                float v0 = acc[mf][nf][0] + bw[nf][0];
                float v1 = acc[mf][nf][1] + bw[nf][1];
                float v2 = acc[mf][nf][2] + bw[nf][0];
                float v3 = acc[mf][nf][3] + bw[nf][1];
                v0 = (v0 < 0.f) ? 0.01f * v0 : v0;
                v1 = (v1 < 0.f) ? 0.01f * v1 : v1;
                v2 = (v2 < 0.f) ? 0.01f * v2 : v2;
                v3 = (v3 < 0.f) ? 0.01f * v3 : v3;
                int cc = nf * 8 + 2 * tig;
                *(__half2*)(p0 + cc) = __floats2half2_rn(v0, v1);
                *(__half2*)(p1 + cc) = __floats2half2_rn(v2, v3);
            }
        }
    } else {
#pragma unroll
        for (int mf = 0; mf < 4; mf++) {
            float* p0 = g_eo + (rowbase + mf * 16 + g) * DIM + nbase + wn;
            float* p1 = p0 + 8 * DIM;
#pragma unroll
            for (int nf = 0; nf < 4; nf++) {
                float v0 = acc[mf][nf][0] + bw[nf][0];
                float v1 = acc[mf][nf][1] + bw[nf][1];
                float v2 = acc[mf][nf][2] + bw[nf][0];
                float v3 = acc[mf][nf][3] + bw[nf][1];
                int cc = nf * 8 + 2 * tig;
                *(float2*)(p0 + cc) = make_float2(v0, v1);
                *(float2*)(p1 + cc) = make_float2(v2, v3);
            }
        }
    }
}

// ---------------- combine ------------------------------------------------------
__global__ void combine_kernel(float* __restrict__ out,
                               const void* __restrict__ topn_p) {
    int tn = load_topn(topn_p);
    size_t idx = (size_t)blockIdx.x * blockDim.x + threadIdx.x;
    if (idx >= (size_t)NTOK * DIM) return;
    int t = (int)(idx >> 10);
    int d = (int)(idx & (DIM - 1));
    float acc = 0.f;
    for (int k = 0; k < tn; k++) {
        int slot = g_slot[t * MAXK + k];
        acc += g_wt[t * MAXK + k] * g_eo[(size_t)slot * DIM + d];
    }
    out[idx] = acc;
}

// ---------------- launch ---------------------------------------------------------
extern "C" void kernel_launch(void* const* d_in, const int* in_sizes, int n_in,
                              void* d_out, int out_size) {
    const float* x   = (const float*)d_in[0];
    const float* gw  = (const float*)d_in[1];
    const float* gb  = (const float*)d_in[2];
    const float* w1  = (const float*)d_in[3];
    const float* b1  = (const float*)d_in[4];
    const float* w2  = (const float*)d_in[5];
    const float* b2  = (const float*)d_in[6];
    const float* w3  = (const float*)d_in[7];
    const float* b3  = (const float*)d_in[8];
    const void*  tp  = d_in[9];
    float* out = (float*)d_out;

    cudaFuncSetAttribute(moe_gemm_tc, cudaFuncAttributeMaxDynamicSharedMemorySize, SMEM_TOTAL);

    __half *xh, *wh;
    cudaGetSymbolAddress((void**)&xh, g_xh);
    cudaGetSymbolAddress((void**)&wh, g_wh);
    size_t lsz = (size_t)NE * KDIM * DIM;

    init_kernel<<<1, 32>>>();
    gating_kernel<<<NTOK / 8, 256>>>(x, gw, gb, tp);

    int n4x = NTOK * DIM / 4;
    int n4w = (int)(lsz / 4);
    f2h_kernel<<<(n4x + 255) / 256, 256>>>(x,  xh,           n4x);
    f2h_kernel<<<(n4w + 255) / 256, 256>>>(w1, wh + 0 * lsz, n4w);
    f2h_kernel<<<(n4w + 255) / 256, 256>>>(w2, wh + 1 * lsz, n4w);
    f2h_kernel<<<(n4w + 255) / 256, 256>>>(w3, wh + 2 * lsz, n4w);

    dim3 grid(DIM / BN, NTOK / BM, NE);    // (4, 64, 8)
    moe_gemm_tc<<<grid, NTHREADS, SMEM_TOTAL>>>(wh + 0 * lsz, b1, 0);
    moe_gemm_tc<<<grid, NTHREADS, SMEM_TOTAL>>>(wh + 1 * lsz, b2, 1);
    moe_gemm_tc<<<grid, NTHREADS, SMEM_TOTAL>>>(wh + 2 * lsz, b3, 2);

    combine_kernel<<<(NTOK * DIM + 255) / 256, 256>>>(out, tp);
}

// round 7
// speedup vs baseline: 6.9778x; 1.0893x over previous
#include <cuda_runtime.h>
#include <cuda_fp16.h>
#include <cstdint>

// Problem constants
#define NTOK  8192
#define DIM   1024
#define NE    8
#define MAXK  8
#define SLAB  8320
#define KDIM  1024

// GEMM tiling (fp16, 2 CTAs/SM)
#define BM 128
#define BN 128
#define BK 64
#define KSTEPS (KDIM / BK)   // 16
#define STAGES 3
#define NTHREADS 256
#define ASZ (BM * BK * 2)    // 16384 B
#define BSZ (BK * BN * 2)    // 16384 B

// dynamic smem layout
#define SM_AROW 0
#define SM_ASZT 1024
#define SM_A    2048
#define SM_B    (SM_A + STAGES * ASZ)
#define SMEM_TOTAL (SM_B + STAGES * BSZ)   // 100352 B -> 2 CTAs/SM

// ---------------- scratch (device globals) ----------------------------------
__device__ int    g_count[NE];
__device__ int    g_tok [NE * NTOK];
__device__ int    g_slot[NTOK * MAXK];
__device__ float  g_wt  [NTOK * MAXK];
__device__ __half g_xh  [(size_t)NTOK * DIM];
__device__ __half g_wh  [(size_t)3 * NE * KDIM * DIM];
__device__ __half g_h1h [(size_t)NE * SLAB * DIM];
__device__ __half g_h2h [(size_t)NE * SLAB * DIM];
__device__ float  g_eo  [(size_t)NE * SLAB * DIM];

// ---------------- PTX helpers ------------------------------------------------
__device__ __forceinline__ uint32_t smem_u32(const void* p) {
    uint32_t a;
    asm("{ .reg .u64 t; cvta.to.shared.u64 t, %1; cvt.u32.u64 %0, t; }" : "=r"(a) : "l"(p));
    return a;
}

__device__ __forceinline__ void cp_async16(uint32_t dst, const void* src, uint32_t sz) {
    asm volatile("cp.async.cg.shared.global [%0], [%1], 16, %2;"
                 :: "r"(dst), "l"(src), "r"(sz) : "memory");
}
#define CP_COMMIT() asm volatile("cp.async.commit_group;" ::: "memory")
#define CP_WAIT1()  asm volatile("cp.async.wait_group 1;" ::: "memory")

__device__ __forceinline__ void ldsm4(uint32_t* r, uint32_t addr) {
    asm volatile("ldmatrix.sync.aligned.m8n8.x4.shared.b16 {%0,%1,%2,%3}, [%4];"
                 : "=r"(r[0]), "=r"(r[1]), "=r"(r[2]), "=r"(r[3]) : "r"(addr));
}
__device__ __forceinline__ void ldsm4t(uint32_t* r, uint32_t addr) {
    asm volatile("ldmatrix.sync.aligned.m8n8.x4.trans.shared.b16 {%0,%1,%2,%3}, [%4];"
                 : "=r"(r[0]), "=r"(r[1]), "=r"(r[2]), "=r"(r[3]) : "r"(addr));
}

__device__ __forceinline__ void mma16(float* c, const uint32_t* a, uint32_t b0, uint32_t b1) {
    asm volatile(
        "mma.sync.aligned.m16n8k16.row.col.f32.f16.f16.f32 "
        "{%0,%1,%2,%3}, {%4,%5,%6,%7}, {%8,%9}, {%0,%1,%2,%3};"
        : "+f"(c[0]), "+f"(c[1]), "+f"(c[2]), "+f"(c[3])
        : "r"(a[0]), "r"(a[1]), "r"(a[2]), "r"(a[3]), "r"(b0), "r"(b1));
}

// ---------------- misc helpers -----------------------------------------------
__device__ __forceinline__ int load_topn(const void* p) {
    int v = *(const int*)p;
    if (v >= 1 && v <= MAXK) return v;
    float f = *(const float*)p;
    int vi = (int)(f + 0.5f);
    if (vi >= 1 && vi <= MAXK) return vi;
    return 2;
}

__global__ void init_kernel() {
    if (threadIdx.x < NE) g_count[threadIdx.x] = 0;
}

// ---------------- fp32 -> fp16 convert ----------------------------------------
__global__ void f2h_kernel(const float* __restrict__ src,
                           __half* __restrict__ dst, int n4) {
    int i = blockIdx.x * blockDim.x + threadIdx.x;
    if (i >= n4) return;
    float4 v = ((const float4*)src)[i];
    __half2 h0 = __floats2half2_rn(v.x, v.y);
    __half2 h1 = __floats2half2_rn(v.z, v.w);
    uint32_t u0 = *(uint32_t*)&h0, u1 = *(uint32_t*)&h1;
    ((uint2*)dst)[i] = make_uint2(u0, u1);
}

// ---------------- gating: one warp per token ---------------------------------
__global__ void gating_kernel(const float* __restrict__ x,
                              const float* __restrict__ gw,
                              const float* __restrict__ gb,
                              const void*  __restrict__ topn_p) {
    int wid  = threadIdx.x >> 5;
    int lane = threadIdx.x & 31;
    int t = blockIdx.x * (blockDim.x >> 5) + wid;
    if (t >= NTOK) return;

    float acc[NE];
#pragma unroll
    for (int e = 0; e < NE; e++) acc[e] = 0.f;

    const float* xr = x + (size_t)t * DIM;
    for (int d = lane; d < DIM; d += 32) {
        float xv = xr[d];
#pragma unroll
        for (int e = 0; e < NE; e++) acc[e] += xv * gw[d * NE + e];
    }
#pragma unroll
    for (int e = 0; e < NE; e++) {
        float v = acc[e];
#pragma unroll
        for (int o = 16; o; o >>= 1) v += __shfl_xor_sync(0xffffffffu, v, o);
        acc[e] = v;
    }

    if (lane == 0) {
        float logit[NE];
#pragma unroll
        for (int e = 0; e < NE; e++) logit[e] = acc[e] + gb[e];
        int tn = load_topn(topn_p);

        int sel[MAXK]; float sl[MAXK]; bool used[NE];
#pragma unroll
        for (int e = 0; e < NE; e++) used[e] = false;
        for (int k = 0; k < tn; k++) {
            int best = -1; float bv = -3.4e38f;
#pragma unroll
            for (int e = 0; e < NE; e++)
                if (!used[e] && logit[e] > bv) { bv = logit[e]; best = e; }
            used[best] = true; sel[k] = best; sl[k] = bv;
        }
        float m = sl[0], s = 0.f;
        for (int k = 0; k < tn; k++) { sl[k] = expf(sl[k] - m); s += sl[k]; }
        float inv = 1.f / s;
        for (int k = 0; k < tn; k++) {
            int e = sel[k];
            int slot = atomicAdd(&g_count[e], 1);
            g_tok [e * NTOK + slot] = t;
            g_slot[t * MAXK + k]    = e * SLAB + slot;
            g_wt  [t * MAXK + k]    = sl[k] * inv;
        }
    }
}

// ---------------- grouped GEMM: fp16 mma m16n8k16, 128x128x64, 2 CTAs/SM -----
// A smem: 128 rows x 64 halves (128B rows), chunk swizzle ch ^= r&7
// B smem: 64 k-rows x 128 halves (256B rows), chunk swizzle ch ^= r&7
__global__ void __launch_bounds__(NTHREADS, 2)
moe_gemm_tc(const __half* __restrict__ W,    // [NE][KDIM][DIM] fp16
            const float* __restrict__ bias,  // [NE][DIM] fp32
            int mode) {
    int e = blockIdx.z;
    int cnt = g_count[e];
    int mbase = blockIdx.y * BM;
    if (mbase >= cnt) return;
    int nbase = blockIdx.x * BN;

    extern __shared__ char smem[];
    int tid = threadIdx.x;
    int wid = tid >> 5;
    int lane = tid & 31;
    int g = lane >> 2, tig = lane & 3;

    const __half* Wb = W + (size_t)e * KDIM * DIM;
    const float*  Bb = bias + (size_t)e * DIM;
    const __half* Asrc = (mode == 1) ? g_h1h : g_h2h;

    const __half** Arow = (const __half**)(smem + SM_AROW);
    int* ArowSz = (int*)(smem + SM_ASZT);
    if (tid < BM) {
        int m = mbase + tid;
        const __half* p = g_xh;
        int sz = 0;
        if (m < cnt) {
            sz = 16;
            if (mode == 0) p = g_xh + (size_t)g_tok[e * NTOK + m] * DIM;
            else           p = Asrc + ((size_t)e * SLAB + m) * DIM;
        }
        Arow[tid] = p;
        ArowSz[tid] = sz;
    }
    __syncthreads();

    uint32_t sA = smem_u32(smem + SM_A);
    uint32_t sB = smem_u32(smem + SM_B);

    auto load_stage = [&](int slot, int kt) {
        int k0 = kt * BK;
        uint32_t as = sA + slot * ASZ;
        uint32_t bs = sB + slot * BSZ;
#pragma unroll
        for (int i = 0; i < 4; i++) {                 // A: 1024 chunks of 16B
            int idx = tid + i * NTHREADS;
            int r = idx >> 3, ch = idx & 7;
            uint32_t dst = as + r * 128 + ((ch ^ (r & 7)) << 4);
            cp_async16(dst, Arow[r] + k0 + ch * 8, ArowSz[r]);
        }
#pragma unroll
        for (int i = 0; i < 4; i++) {                 // B: 1024 chunks of 16B
            int idx = tid + i * NTHREADS;
            int r = idx >> 4, ch = idx & 15;
            uint32_t dst = bs + r * 256 + ((ch ^ (r & 7)) << 4);
            cp_async16(dst, Wb + (size_t)(k0 + r) * DIM + nbase + ch * 8, 16);
        }
    };

    // prologue: 2 stages in flight
    load_stage(0, 0); CP_COMMIT();
    load_stage(1, 1); CP_COMMIT();

    // warp tile 64x32: 2 warp-rows x 4 warp-cols
    int wm = (wid & 1) * 64;
    int wn = (wid >> 1) * 32;

    // precomputed ldmatrix offsets
    int l15 = lane & 15, hi = lane >> 4, l7 = lane & 7;
    uint32_t aRowOff = (uint32_t)(wm + l15) * 128;        // + mf*2048 + swcA[ks]
    uint32_t swcA[4];
#pragma unroll
    for (int ks = 0; ks < 4; ks++)
        swcA[ks] = (uint32_t)(((ks * 2 + hi) ^ l7) << 4);
    uint32_t bRowOff = (uint32_t)l15 * 256;               // + ks*4096 + cBn[nt]
    int nch = (wn >> 3);
    uint32_t cBn[2];
#pragma unroll
    for (int nt = 0; nt < 2; nt++)
        cBn[nt] = (uint32_t)((((nch + nt * 2) + hi) ^ l7) << 4);

    float acc[4][4][4];
#pragma unroll
    for (int i = 0; i < 4; i++)
#pragma unroll
        for (int j = 0; j < 4; j++)
#pragma unroll
            for (int q = 0; q < 4; q++) acc[i][j][q] = 0.f;

    int slot = 0;
    for (int kt = 0; kt < KSTEPS; kt++) {
        CP_WAIT1();
        __syncthreads();
        if (kt + 2 < KSTEPS) {
            int ps = slot + 2; if (ps >= STAGES) ps -= STAGES;
            load_stage(ps, kt + 2);
        }
        CP_COMMIT();

        uint32_t as = sA + slot * ASZ + aRowOff;
        uint32_t bs = sB + slot * BSZ + bRowOff;
#pragma unroll
        for (int ks = 0; ks < 4; ks++) {
            uint32_t a[4][4];
#pragma unroll
            for (int mf = 0; mf < 4; mf++)
                ldsm4(a[mf], as + mf * 2048 + swcA[ks]);
            uint32_t b[2][4];
            uint32_t bk = bs + ks * 4096;
            ldsm4t(b[0], bk + cBn[0]);
            ldsm4t(b[1], bk + cBn[1]);
#pragma unroll
            for (int mf = 0; mf < 4; mf++) {
                mma16(acc[mf][0], a[mf], b[0][0], b[0][1]);
                mma16(acc[mf][1], a[mf], b[0][2], b[0][3]);
                mma16(acc[mf][2], a[mf], b[1][0], b[1][1]);
                mma16(acc[mf][3], a[mf], b[1][2], b[1][3]);
            }
        }
        if (++slot == STAGES) slot = 0;
    }

    // epilogue: bias + optional LeakyReLU; fp16 out for modes 0/1, fp32 for mode 2
    float bw[4][2];
#pragma unroll
    for (int nf = 0; nf < 4; nf++) {
        int cc = nbase + wn + nf * 8 + 2 * tig;
        bw[nf][0] = Bb[cc];
        bw[nf][1] = Bb[cc + 1];
    }
    size_t rowbase = (size_t)e * SLAB + mbase + wm;
    if (mode != 2) {
        __half* OutH = (mode == 1) ? g_h2h : g_h1h;
#pragma unroll
        for (int mf = 0; mf < 4; mf++) {
            __half* p0 = OutH + (rowbase + mf * 16 + g) * DIM + nbase + wn;
            __half* p1 = p0 + 8 * DIM;
#pragma unroll
            for (int nf = 0; nf < 4; nf++) {
                float v0 = acc[mf][nf][0] + bw[nf][0];
                float v1 = acc[mf][nf][1] + bw[nf][1];
                float v2 = acc[mf][nf][2] + bw[nf][0];
                float v3 = acc[mf][nf][3] + bw[nf][1];
                v0 = (v0 < 0.f) ? 0.01f * v0 : v0;
                v1 = (v1 < 0.f) ? 0.01f * v1 : v1;
                v2 = (v2 < 0.f) ? 0.01f * v2 : v2;
                v3 = (v3 < 0.f) ? 0.01f * v3 : v3;
                int cc = nf * 8 + 2 * tig;
                *(__half2*)(p0 + cc) = __floats2half2_rn(v0, v1);
                *(__half2*)(p1 + cc) = __floats2half2_rn(v2, v3);
            }
        }
    } else {
#pragma unroll
        for (int mf = 0; mf < 4; mf++) {
            float* p0 = g_eo + (rowbase + mf * 16 + g) * DIM + nbase + wn;
            float* p1 = p0 + 8 * DIM;
#pragma unroll
            for (int nf = 0; nf < 4; nf++) {
                float v0 = acc[mf][nf][0] + bw[nf][0];
                float v1 = acc[mf][nf][1] + bw[nf][1];
                float v2 = acc[mf][nf][2] + bw[nf][0];
                float v3 = acc[mf][nf][3] + bw[nf][1];
                int cc = nf * 8 + 2 * tig;
                *(float2*)(p0 + cc) = make_float2(v0, v1);
                *(float2*)(p1 + cc) = make_float2(v2, v3);
            }
        }
    }
}

// ---------------- combine ------------------------------------------------------
__global__ void combine_kernel(float* __restrict__ out,
                               const void* __restrict__ topn_p) {
    int tn = load_topn(topn_p);
    size_t idx = (size_t)blockIdx.x * blockDim.x + threadIdx.x;
    if (idx >= (size_t)NTOK * DIM) return;
    int t = (int)(idx >> 10);
    int d = (int)(idx & (DIM - 1));
    float acc = 0.f;
    for (int k = 0; k < tn; k++) {
        int slot = g_slot[t * MAXK + k];
        acc += g_wt[t * MAXK + k] * g_eo[(size_t)slot * DIM + d];
    }
    out[idx] = acc;
}

// ---------------- launch ---------------------------------------------------------
extern "C" void kernel_launch(void* const* d_in, const int* in_sizes, int n_in,
                              void* d_out, int out_size) {
    const float* x   = (const float*)d_in[0];
    const float* gw  = (const float*)d_in[1];
    const float* gb  = (const float*)d_in[2];
    const float* w1  = (const float*)d_in[3];
    const float* b1  = (const float*)d_in[4];
    const float* w2  = (const float*)d_in[5];
    const float* b2  = (const float*)d_in[6];
    const float* w3  = (const float*)d_in[7];
    const float* b3  = (const float*)d_in[8];
    const void*  tp  = d_in[9];
    float* out = (float*)d_out;

    cudaFuncSetAttribute(moe_gemm_tc, cudaFuncAttributeMaxDynamicSharedMemorySize, SMEM_TOTAL);

    __half *xh, *wh;
    cudaGetSymbolAddress((void**)&xh, g_xh);
    cudaGetSymbolAddress((void**)&wh, g_wh);
    size_t lsz = (size_t)NE * KDIM * DIM;

    init_kernel<<<1, 32>>>();
    gating_kernel<<<NTOK / 8, 256>>>(x, gw, gb, tp);

    int n4x = NTOK * DIM / 4;
    int n4w = (int)(lsz / 4);
    f2h_kernel<<<(n4x + 255) / 256, 256>>>(x,  xh,           n4x);
    f2h_kernel<<<(n4w + 255) / 256, 256>>>(w1, wh + 0 * lsz, n4w);
    f2h_kernel<<<(n4w + 255) / 256, 256>>>(w2, wh + 1 * lsz, n4w);
    f2h_kernel<<<(n4w + 255) / 256, 256>>>(w3, wh + 2 * lsz, n4w);

    dim3 grid(DIM / BN, NTOK / BM, NE);    // (8, 64, 8)
    moe_gemm_tc<<<grid, NTHREADS, SMEM_TOTAL>>>(wh + 0 * lsz, b1, 0);
    moe_gemm_tc<<<grid, NTHREADS, SMEM_TOTAL>>>(wh + 1 * lsz, b2, 1);
    moe_gemm_tc<<<grid, NTHREADS, SMEM_TOTAL>>>(wh + 2 * lsz, b3, 2);

    combine_kernel<<<(NTOK * DIM + 255) / 256, 256>>>(out, tp);
}

// round 8
// speedup vs baseline: 7.4725x; 1.0709x over previous
#include <cuda_runtime.h>
#include <cuda_fp16.h>
#include <cstdint>

// Problem constants
#define NTOK  8192
#define DIM   1024
#define NE    8
#define MAXK  8
#define SLAB  8320
#define KDIM  1024

// GEMM tiling (fp16, 2 CTAs/SM)
#define BM 128
#define BN 128
#define BK 64
#define KSTEPS (KDIM / BK)   // 16
#define STAGES 3
#define NTHREADS 256
#define ASZ (BM * BK * 2)    // 16384 B
#define BSZ (BK * BN * 2)    // 16384 B

// dynamic smem layout
#define SM_AROW 0
#define SM_ASZT 1024
#define SM_A    2048
#define SM_B    (SM_A + STAGES * ASZ)
#define SMEM_TOTAL (SM_B + STAGES * BSZ)   // 100352 B -> 2 CTAs/SM

// ---------------- scratch (device globals) ----------------------------------
__device__ int    g_count[NE];
__device__ int    g_tok [NE * NTOK];
__device__ int    g_slot[NTOK * MAXK];
__device__ float  g_wt  [NTOK * MAXK];
__device__ __half g_xh  [(size_t)NTOK * DIM];
__device__ __half g_wh  [(size_t)3 * NE * KDIM * DIM];
__device__ __half g_h1h [(size_t)NE * SLAB * DIM];
__device__ __half g_h2h [(size_t)NE * SLAB * DIM];
__device__ float  g_eo  [(size_t)NE * SLAB * DIM];

// ---------------- PTX helpers ------------------------------------------------
__device__ __forceinline__ uint32_t smem_u32(const void* p) {
    uint32_t a;
    asm("{ .reg .u64 t; cvta.to.shared.u64 t, %1; cvt.u32.u64 %0, t; }" : "=r"(a) : "l"(p));
    return a;
}

__device__ __forceinline__ void cp_async16(uint32_t dst, const void* src, uint32_t sz) {
    asm volatile("cp.async.cg.shared.global [%0], [%1], 16, %2;"
                 :: "r"(dst), "l"(src), "r"(sz) : "memory");
}
#define CP_COMMIT() asm volatile("cp.async.commit_group;" ::: "memory")
#define CP_WAIT1()  asm volatile("cp.async.wait_group 1;" ::: "memory")

__device__ __forceinline__ void ldsm4(uint32_t* r, uint32_t addr) {
    asm volatile("ldmatrix.sync.aligned.m8n8.x4.shared.b16 {%0,%1,%2,%3}, [%4];"
                 : "=r"(r[0]), "=r"(r[1]), "=r"(r[2]), "=r"(r[3]) : "r"(addr));
}
__device__ __forceinline__ void ldsm4t(uint32_t* r, uint32_t addr) {
    asm volatile("ldmatrix.sync.aligned.m8n8.x4.trans.shared.b16 {%0,%1,%2,%3}, [%4];"
                 : "=r"(r[0]), "=r"(r[1]), "=r"(r[2]), "=r"(r[3]) : "r"(addr));
}

__device__ __forceinline__ void mma16(float* c, const uint32_t* a, uint32_t b0, uint32_t b1) {
    asm volatile(
        "mma.sync.aligned.m16n8k16.row.col.f32.f16.f16.f32 "
        "{%0,%1,%2,%3}, {%4,%5,%6,%7}, {%8,%9}, {%0,%1,%2,%3};"
        : "+f"(c[0]), "+f"(c[1]), "+f"(c[2]), "+f"(c[3])
        : "r"(a[0]), "r"(a[1]), "r"(a[2]), "r"(a[3]), "r"(b0), "r"(b1));
}

// ---------------- misc helpers -----------------------------------------------
__device__ __forceinline__ int load_topn(const void* p) {
    int v = *(const int*)p;
    if (v >= 1 && v <= MAXK) return v;
    float f = *(const float*)p;
    int vi = (int)(f + 0.5f);
    if (vi >= 1 && vi <= MAXK) return vi;
    return 2;
}

__global__ void init_kernel() {
    if (threadIdx.x < NE) g_count[threadIdx.x] = 0;
}

// ---------------- fp32 -> fp16 convert (weights, all 3 layers) ---------------
__global__ void f2h_kernel(const float* __restrict__ s1,
                           const float* __restrict__ s2,
                           const float* __restrict__ s3,
                           __half* __restrict__ dst, int n4) {
    int i = blockIdx.x * blockDim.x + threadIdx.x;
    if (i >= 3 * n4) return;
    int layer = i / n4;
    int j = i - layer * n4;
    const float* src = (layer == 0) ? s1 : (layer == 1) ? s2 : s3;
    float4 v = ((const float4*)src)[j];
    __half2 h0 = __floats2half2_rn(v.x, v.y);
    __half2 h1 = __floats2half2_rn(v.z, v.w);
    uint32_t u0 = *(uint32_t*)&h0, u1 = *(uint32_t*)&h1;
    ((uint2*)dst)[i] = make_uint2(u0, u1);
}

// ---------------- gating: one warp per token; also emits fp16 x --------------
__global__ void gating_kernel(const float* __restrict__ x,
                              const float* __restrict__ gw,
                              const float* __restrict__ gb,
                              const void*  __restrict__ topn_p) {
    int wid  = threadIdx.x >> 5;
    int lane = threadIdx.x & 31;
    int t = blockIdx.x * (blockDim.x >> 5) + wid;
    if (t >= NTOK) return;

    float acc[NE];
#pragma unroll
    for (int e = 0; e < NE; e++) acc[e] = 0.f;

    const float* xr = x + (size_t)t * DIM;
    __half* xo = g_xh + (size_t)t * DIM;
    for (int d = lane; d < DIM; d += 32) {
        float xv = xr[d];
        xo[d] = __float2half_rn(xv);          // fused fp16 conversion
#pragma unroll
        for (int e = 0; e < NE; e++) acc[e] += xv * gw[d * NE + e];
    }
#pragma unroll
    for (int e = 0; e < NE; e++) {
        float v = acc[e];
#pragma unroll
        for (int o = 16; o; o >>= 1) v += __shfl_xor_sync(0xffffffffu, v, o);
        acc[e] = v;
    }

    if (lane == 0) {
        float logit[NE];
#pragma unroll
        for (int e = 0; e < NE; e++) logit[e] = acc[e] + gb[e];
        int tn = load_topn(topn_p);

        int sel[MAXK]; float sl[MAXK]; bool used[NE];
#pragma unroll
        for (int e = 0; e < NE; e++) used[e] = false;
        for (int k = 0; k < tn; k++) {
            int best = -1; float bv = -3.4e38f;
#pragma unroll
            for (int e = 0; e < NE; e++)
                if (!used[e] && logit[e] > bv) { bv = logit[e]; best = e; }
            used[best] = true; sel[k] = best; sl[k] = bv;
        }
        float m = sl[0], s = 0.f;
        for (int k = 0; k < tn; k++) { sl[k] = expf(sl[k] - m); s += sl[k]; }
        float inv = 1.f / s;
        for (int k = 0; k < tn; k++) {
            int e = sel[k];
            int slot = atomicAdd(&g_count[e], 1);
            g_tok [e * NTOK + slot] = t;
            g_slot[t * MAXK + k]    = e * SLAB + slot;
            g_wt  [t * MAXK + k]    = sl[k] * inv;
        }
    }
}

// ---------------- grouped GEMM: fp16 mma m16n8k16, 128x128x64, 2 CTAs/SM -----
__global__ void __launch_bounds__(NTHREADS, 2)
moe_gemm_tc(const __half* __restrict__ W,    // [NE][KDIM][DIM] fp16
            const float* __restrict__ bias,  // [NE][DIM] fp32
            int mode) {
    int e = blockIdx.z;
    int cnt = g_count[e];
    int mbase = blockIdx.y * BM;
    if (mbase >= cnt) return;
    int nbase = blockIdx.x * BN;

    extern __shared__ char smem[];
    int tid = threadIdx.x;
    int wid = tid >> 5;
    int lane = tid & 31;
    int g = lane >> 2, tig = lane & 3;

    const __half* Wb = W + (size_t)e * KDIM * DIM;
    const float*  Bb = bias + (size_t)e * DIM;
    const __half* Asrc = (mode == 1) ? g_h1h : g_h2h;

    const __half** Arow = (const __half**)(smem + SM_AROW);
    int* ArowSz = (int*)(smem + SM_ASZT);
    if (tid < BM) {
        int m = mbase + tid;
        const __half* p = g_xh;
        int sz = 0;
        if (m < cnt) {
            sz = 16;
            if (mode == 0) p = g_xh + (size_t)g_tok[e * NTOK + m] * DIM;
            else           p = Asrc + ((size_t)e * SLAB + m) * DIM;
        }
        Arow[tid] = p;
        ArowSz[tid] = sz;
    }
    __syncthreads();

    uint32_t sA = smem_u32(smem + SM_A);
    uint32_t sB = smem_u32(smem + SM_B);

    auto load_stage = [&](int slot, int kt) {
        int k0 = kt * BK;
        uint32_t as = sA + slot * ASZ;
        uint32_t bs = sB + slot * BSZ;
#pragma unroll
        for (int i = 0; i < 4; i++) {                 // A: 1024 chunks of 16B
            int idx = tid + i * NTHREADS;
            int r = idx >> 3, ch = idx & 7;
            uint32_t dst = as + r * 128 + ((ch ^ (r & 7)) << 4);
            cp_async16(dst, Arow[r] + k0 + ch * 8, ArowSz[r]);
        }
#pragma unroll
        for (int i = 0; i < 4; i++) {                 // B: 1024 chunks of 16B
            int idx = tid + i * NTHREADS;
            int r = idx >> 4, ch = idx & 15;
            uint32_t dst = bs + r * 256 + ((ch ^ (r & 7)) << 4);
            cp_async16(dst, Wb + (size_t)(k0 + r) * DIM + nbase + ch * 8, 16);
        }
    };

    load_stage(0, 0); CP_COMMIT();
    load_stage(1, 1); CP_COMMIT();

    int wm = (wid & 1) * 64;
    int wn = (wid >> 1) * 32;

    int l15 = lane & 15, hi = lane >> 4, l7 = lane & 7;
    uint32_t aRowOff = (uint32_t)(wm + l15) * 128;
    uint32_t swcA[4];
#pragma unroll
    for (int ks = 0; ks < 4; ks++)
        swcA[ks] = (uint32_t)(((ks * 2 + hi) ^ l7) << 4);
    uint32_t bRowOff = (uint32_t)l15 * 256;
    int nch = (wn >> 3);
    uint32_t cBn[2];
#pragma unroll
    for (int nt = 0; nt < 2; nt++)
        cBn[nt] = (uint32_t)((((nch + nt * 2) + hi) ^ l7) << 4);

    float acc[4][4][4];
#pragma unroll
    for (int i = 0; i < 4; i++)
#pragma unroll
        for (int j = 0; j < 4; j++)
#pragma unroll
            for (int q = 0; q < 4; q++) acc[i][j][q] = 0.f;

    int slot = 0;
    for (int kt = 0; kt < KSTEPS; kt++) {
        CP_WAIT1();
        __syncthreads();
        if (kt + 2 < KSTEPS) {
            int ps = slot + 2; if (ps >= STAGES) ps -= STAGES;
            load_stage(ps, kt + 2);
        }
        CP_COMMIT();

        uint32_t as = sA + slot * ASZ + aRowOff;
        uint32_t bs = sB + slot * BSZ + bRowOff;
#pragma unroll
        for (int ks = 0; ks < 4; ks++) {
            uint32_t a[4][4];
#pragma unroll
            for (int mf = 0; mf < 4; mf++)
                ldsm4(a[mf], as + mf * 2048 + swcA[ks]);
            uint32_t b[2][4];
            uint32_t bk = bs + ks * 4096;
            ldsm4t(b[0], bk + cBn[0]);
            ldsm4t(b[1], bk + cBn[1]);
#pragma unroll
            for (int mf = 0; mf < 4; mf++) {
                mma16(acc[mf][0], a[mf], b[0][0], b[0][1]);
                mma16(acc[mf][1], a[mf], b[0][2], b[0][3]);
                mma16(acc[mf][2], a[mf], b[1][0], b[1][1]);
                mma16(acc[mf][3], a[mf], b[1][2], b[1][3]);
            }
        }
        if (++slot == STAGES) slot = 0;
    }

    float bw[4][2];
#pragma unroll
    for (int nf = 0; nf < 4; nf++) {
        int cc = nbase + wn + nf * 8 + 2 * tig;
        bw[nf][0] = Bb[cc];
        bw[nf][1] = Bb[cc + 1];
    }
    size_t rowbase = (size_t)e * SLAB + mbase + wm;
    if (mode != 2) {
        __half* OutH = (mode == 1) ? g_h2h : g_h1h;
#pragma unroll
        for (int mf = 0; mf < 4; mf++) {
            __half* p0 = OutH + (rowbase + mf * 16 + g) * DIM + nbase + wn;
            __half* p1 = p0 + 8 * DIM;
#pragma unroll
            for (int nf = 0; nf < 4; nf++) {
                float v0 = acc[mf][nf][0] + bw[nf][0];
                float v1 = acc[mf][nf][1] + bw[nf][1];
                float v2 = acc[mf][nf][2] + bw[nf][0];
                float v3 = acc[mf][nf][3] + bw[nf][1];
                v0 = (v0 < 0.f) ? 0.01f * v0 : v0;
                v1 = (v1 < 0.f) ? 0.01f * v1 : v1;
                v2 = (v2 < 0.f) ? 0.01f * v2 : v2;
                v3 = (v3 < 0.f) ? 0.01f * v3 : v3;
                int cc = nf * 8 + 2 * tig;
                *(__half2*)(p0 + cc) = __floats2half2_rn(v0, v1);
                *(__half2*)(p1 + cc) = __floats2half2_rn(v2, v3);
            }
        }
    } else {
#pragma unroll
        for (int mf = 0; mf < 4; mf++) {
            float* p0 = g_eo + (rowbase + mf * 16 + g) * DIM + nbase + wn;
            float* p1 = p0 + 8 * DIM;
#pragma unroll
            for (int nf = 0; nf < 4; nf++) {
                float v0 = acc[mf][nf][0] + bw[nf][0];
                float v1 = acc[mf][nf][1] + bw[nf][1];
                float v2 = acc[mf][nf][2] + bw[nf][0];
                float v3 = acc[mf][nf][3] + bw[nf][1];
                int cc = nf * 8 + 2 * tig;
                *(float2*)(p0 + cc) = make_float2(v0, v1);
                *(float2*)(p1 + cc) = make_float2(v2, v3);
            }
        }
    }
}

// ---------------- combine (float4 vectorized) ---------------------------------
__global__ void combine_kernel(float* __restrict__ out,
                               const void* __restrict__ topn_p) {
    int tn = load_topn(topn_p);
    int idx = blockIdx.x * blockDim.x + threadIdx.x;      // over NTOK*DIM/4
    if (idx >= NTOK * DIM / 4) return;
    int t = idx >> 8;                                      // DIM/4 = 256
    int d4 = (idx & 255) << 2;
    float4 acc = make_float4(0.f, 0.f, 0.f, 0.f);
    for (int k = 0; k < tn; k++) {
        int slot = g_slot[t * MAXK + k];
        float w = g_wt[t * MAXK + k];
        float4 v = *(const float4*)(g_eo + (size_t)slot * DIM + d4);
        acc.x += w * v.x; acc.y += w * v.y;
        acc.z += w * v.z; acc.w += w * v.w;
    }
    *(float4*)(out + (size_t)t * DIM + d4) = acc;
}

// ---------------- launch ---------------------------------------------------------
extern "C" void kernel_launch(void* const* d_in, const int* in_sizes, int n_in,
                              void* d_out, int out_size) {
    const float* x   = (const float*)d_in[0];
    const float* gw  = (const float*)d_in[1];
    const float* gb  = (const float*)d_in[2];
    const float* w1  = (const float*)d_in[3];
    const float* b1  = (const float*)d_in[4];
    const float* w2  = (const float*)d_in[5];
    const float* b2  = (const float*)d_in[6];
    const float* w3  = (const float*)d_in[7];
    const float* b3  = (const float*)d_in[8];
    const void*  tp  = d_in[9];
    float* out = (float*)d_out;

    cudaFuncSetAttribute(moe_gemm_tc, cudaFuncAttributeMaxDynamicSharedMemorySize, SMEM_TOTAL);

    __half *wh;
    cudaGetSymbolAddress((void**)&wh, g_wh);
    size_t lsz = (size_t)NE * KDIM * DIM;

    init_kernel<<<1, 32>>>();
    gating_kernel<<<NTOK / 8, 256>>>(x, gw, gb, tp);

    int n4w = (int)(lsz / 4);
    f2h_kernel<<<(3 * n4w + 255) / 256, 256>>>(w1, w2, w3, wh, n4w);

    dim3 grid(DIM / BN, NTOK / BM, NE);    // (8, 64, 8)
    moe_gemm_tc<<<grid, NTHREADS, SMEM_TOTAL>>>(wh + 0 * lsz, b1, 0);
    moe_gemm_tc<<<grid, NTHREADS, SMEM_TOTAL>>>(wh + 1 * lsz, b2, 1);
    moe_gemm_tc<<<grid, NTHREADS, SMEM_TOTAL>>>(wh + 2 * lsz, b3, 2);

    combine_kernel<<<(NTOK * DIM / 4 + 255) / 256, 256>>>(out, tp);
}